// round 1
// baseline (speedup 1.0000x reference)
#include <cuda_runtime.h>
#include <math.h>

#define SQ    2048
#define DIM   2048
#define NH    16
#define HD    128
#define BATCH 2
#define NROWS 4096      // B*S
#define DLCA  4096
#define DFF   8192

// ---------------- scratch (static device globals; no allocs allowed) -------
__device__ float g_hn  [(size_t)NROWS*DIM];
__device__ float g_q   [(size_t)NROWS*DIM];
__device__ float g_k   [(size_t)NROWS*DIM];
__device__ float g_v   [(size_t)NROWS*DIM];
__device__ float g_attn[(size_t)NROWS*DIM];
__device__ float g_ao  [(size_t)NROWS*DIM];
__device__ float g_h   [(size_t)NROWS*DIM];
__device__ float g_t1  [(size_t)NROWS*DIM];
__device__ float g_mlp [(size_t)NROWS*DIM];
__device__ float g_b   [(size_t)NROWS*DLCA];
__device__ float g_u   [(size_t)NROWS*DLCA];
__device__ float g_a   [(size_t)NROWS*DLCA];
__device__ float g_t2  [(size_t)NROWS*DLCA];
__device__ float g_gate[(size_t)NROWS*DFF];
__device__ float g_up  [(size_t)NROWS*DFF];
__device__ float g_diag[DLCA];

// ---------------- SGEMM: C[M,N] = A[M,K] @ B[K,N], all row-major -----------
#define BM 128
#define BN 128
#define BK 8

__global__ __launch_bounds__(256) void sgemm_nn(
    const float* __restrict__ A, const float* __restrict__ B, float* __restrict__ C,
    int M, int N, int K)
{
    __shared__ float As[BK][BM];
    __shared__ float Bs[BK][BN];
    int tid = threadIdx.x;
    int bx = blockIdx.x, by = blockIdx.y;
    const float* Ab = A + (size_t)by * BM * K;
    const float* Bb = B + (size_t)bx * BN;
    int aRow = tid >> 1,  aCol = (tid & 1) << 2;
    int bRow = tid >> 5,  bCol = (tid & 31) << 2;
    int tr = (tid >> 4) << 3, tc = (tid & 15) << 3;

    float acc[8][8];
#pragma unroll
    for (int i = 0; i < 8; ++i)
#pragma unroll
        for (int j = 0; j < 8; ++j) acc[i][j] = 0.f;

    for (int k0 = 0; k0 < K; k0 += BK) {
        float4 av = *(const float4*)(Ab + (size_t)aRow * K + k0 + aCol);
        float4 bv = *(const float4*)(Bb + (size_t)(k0 + bRow) * N + bCol);
        As[aCol + 0][aRow] = av.x; As[aCol + 1][aRow] = av.y;
        As[aCol + 2][aRow] = av.z; As[aCol + 3][aRow] = av.w;
        *(float4*)&Bs[bRow][bCol] = bv;
        __syncthreads();
#pragma unroll
        for (int k = 0; k < BK; ++k) {
            float4 t0 = *(const float4*)&As[k][tr];
            float4 t1 = *(const float4*)&As[k][tr + 4];
            float4 u0 = *(const float4*)&Bs[k][tc];
            float4 u1 = *(const float4*)&Bs[k][tc + 4];
            float ar[8] = {t0.x, t0.y, t0.z, t0.w, t1.x, t1.y, t1.z, t1.w};
            float br[8] = {u0.x, u0.y, u0.z, u0.w, u1.x, u1.y, u1.z, u1.w};
#pragma unroll
            for (int i = 0; i < 8; ++i)
#pragma unroll
                for (int j = 0; j < 8; ++j)
                    acc[i][j] = fmaf(ar[i], br[j], acc[i][j]);
        }
        __syncthreads();
    }

    float* Cb = C + (size_t)(by * BM + tr) * N + bx * BN + tc;
#pragma unroll
    for (int i = 0; i < 8; ++i) {
        float4 c0 = make_float4(acc[i][0], acc[i][1], acc[i][2], acc[i][3]);
        float4 c1 = make_float4(acc[i][4], acc[i][5], acc[i][6], acc[i][7]);
        *(float4*)(Cb + (size_t)i * N)     = c0;
        *(float4*)(Cb + (size_t)i * N + 4) = c1;
    }
}

// C[M,N] = A[M,K] @ Bt^T  where Bt is [N,K] row-major (NT gemm)
__global__ __launch_bounds__(256) void sgemm_nt(
    const float* __restrict__ A, const float* __restrict__ Bt, float* __restrict__ C,
    int M, int N, int K)
{
    __shared__ float As[BK][BM];
    __shared__ float Bs[BK][BN];
    int tid = threadIdx.x;
    int bx = blockIdx.x, by = blockIdx.y;
    const float* Ab = A  + (size_t)by * BM * K;
    const float* Bb = Bt + (size_t)bx * BN * K;
    int aRow = tid >> 1, aCol = (tid & 1) << 2;
    int tr = (tid >> 4) << 3, tc = (tid & 15) << 3;

    float acc[8][8];
#pragma unroll
    for (int i = 0; i < 8; ++i)
#pragma unroll
        for (int j = 0; j < 8; ++j) acc[i][j] = 0.f;

    for (int k0 = 0; k0 < K; k0 += BK) {
        float4 av = *(const float4*)(Ab + (size_t)aRow * K + k0 + aCol);
        float4 bv = *(const float4*)(Bb + (size_t)aRow * K + k0 + aCol);
        As[aCol + 0][aRow] = av.x; As[aCol + 1][aRow] = av.y;
        As[aCol + 2][aRow] = av.z; As[aCol + 3][aRow] = av.w;
        Bs[aCol + 0][aRow] = bv.x; Bs[aCol + 1][aRow] = bv.y;
        Bs[aCol + 2][aRow] = bv.z; Bs[aCol + 3][aRow] = bv.w;
        __syncthreads();
#pragma unroll
        for (int k = 0; k < BK; ++k) {
            float4 t0 = *(const float4*)&As[k][tr];
            float4 t1 = *(const float4*)&As[k][tr + 4];
            float4 u0 = *(const float4*)&Bs[k][tc];
            float4 u1 = *(const float4*)&Bs[k][tc + 4];
            float ar[8] = {t0.x, t0.y, t0.z, t0.w, t1.x, t1.y, t1.z, t1.w};
            float br[8] = {u0.x, u0.y, u0.z, u0.w, u1.x, u1.y, u1.z, u1.w};
#pragma unroll
            for (int i = 0; i < 8; ++i)
#pragma unroll
                for (int j = 0; j < 8; ++j)
                    acc[i][j] = fmaf(ar[i], br[j], acc[i][j]);
        }
        __syncthreads();
    }

    float* Cb = C + (size_t)(by * BM + tr) * N + bx * BN + tc;
#pragma unroll
    for (int i = 0; i < 8; ++i) {
        float4 c0 = make_float4(acc[i][0], acc[i][1], acc[i][2], acc[i][3]);
        float4 c1 = make_float4(acc[i][4], acc[i][5], acc[i][6], acc[i][7]);
        *(float4*)(Cb + (size_t)i * N)     = c0;
        *(float4*)(Cb + (size_t)i * N + 4) = c1;
    }
}

// ---------------- RMSNorm ---------------------------------------------------
__global__ __launch_bounds__(256) void rmsnorm_kernel(
    const float* __restrict__ x, const float* __restrict__ w, float* __restrict__ out)
{
    __shared__ float red[8];
    int row = blockIdx.x, tid = threadIdx.x;
    const float* xr = x + (size_t)row * DIM;
    float4 v[2];
    float ss = 0.f;
#pragma unroll
    for (int p = 0; p < 2; ++p) {
        v[p] = *(const float4*)(xr + p * 1024 + tid * 4);
        ss += v[p].x * v[p].x + v[p].y * v[p].y + v[p].z * v[p].z + v[p].w * v[p].w;
    }
#pragma unroll
    for (int off = 16; off; off >>= 1) ss += __shfl_xor_sync(~0u, ss, off);
    if ((tid & 31) == 0) red[tid >> 5] = ss;
    __syncthreads();
    if (tid == 0) {
        float t = 0.f;
#pragma unroll
        for (int i = 0; i < 8; ++i) t += red[i];
        red[0] = rsqrtf(t / (float)DIM + 1e-6f);
    }
    __syncthreads();
    float inv = red[0];
    float* orow = out + (size_t)row * DIM;
#pragma unroll
    for (int p = 0; p < 2; ++p) {
        int c = p * 1024 + tid * 4;
        float4 wv = *(const float4*)(w + c);
        float4 o;
        o.x = v[p].x * inv * wv.x; o.y = v[p].y * inv * wv.y;
        o.z = v[p].z * inv * wv.z; o.w = v[p].w * inv * wv.w;
        *(float4*)(orow + c) = o;
    }
}

// ---------------- RoPE (in-place on q and k) --------------------------------
__global__ void rope_kernel(float* __restrict__ q, float* __restrict__ k)
{
    int idx = blockIdx.x * blockDim.x + threadIdx.x;
    if (idx >= NROWS * NH * 64) return;
    int i   = idx & 63;
    int h   = (idx >> 6) & (NH - 1);
    int row = idx >> 10;
    int pos = row & (SQ - 1);
    float inv = (float)exp(-((double)(2 * i) / (double)HD) * 9.210340371976184); // ln(1e4)
    float ang = (float)pos * inv;
    float sn, cs;
    sincosf(ang, &sn, &cs);
    size_t base = (size_t)row * DIM + (size_t)h * HD;
    float a = q[base + i], b = q[base + i + 64];
    q[base + i]      = a * cs - b * sn;
    q[base + i + 64] = b * cs + a * sn;
    a = k[base + i]; b = k[base + i + 64];
    k[base + i]      = a * cs - b * sn;
    k[base + i + 64] = b * cs + a * sn;
}

// ---------------- Flash attention (causal), 64x64 tiles ---------------------
// smem: Qs[64][128] | Ks[64][132] | Vs[64][128] | Ps[64][64]
#define ATTN_SMEM_FLOATS (64*128 + 64*132 + 64*128 + 64*64)
#define ATTN_SMEM_BYTES  (ATTN_SMEM_FLOATS * 4)

__global__ __launch_bounds__(256) void attn_kernel(
    const float* __restrict__ Q, const float* __restrict__ K,
    const float* __restrict__ V, float* __restrict__ O)
{
    extern __shared__ float sm[];
    float* Qs = sm;                       // 8192
    float* Ks = sm + 8192;                // 8448 (stride 132)
    float* Vs = sm + 8192 + 8448;         // 8192
    float* Ps = sm + 8192 + 8448 + 8192;  // 4096

    int qt = blockIdx.x, h = blockIdx.y, b = blockIdx.z;
    int tid = threadIdx.x;
    int ty = tid >> 4, tx = tid & 15;
    int qr0 = ty * 4;       // 4 query rows per thread
    int dc0 = tx * 8;       // 8 output dims per thread

    const float* Qb = Q + (size_t)b * SQ * DIM + (size_t)h * HD;
    const float* Kb = K + (size_t)b * SQ * DIM + (size_t)h * HD;
    const float* Vb = V + (size_t)b * SQ * DIM + (size_t)h * HD;

    for (int i = tid; i < 64 * 32; i += 256) {
        int r = i >> 5, c = (i & 31) << 2;
        *(float4*)&Qs[r * 128 + c] =
            *(const float4*)(Qb + (size_t)(qt * 64 + r) * DIM + c);
    }

    float m[4], l[4], o[4][8];
#pragma unroll
    for (int i = 0; i < 4; ++i) {
        m[i] = -3.0e38f; l[i] = 0.f;
#pragma unroll
        for (int d = 0; d < 8; ++d) o[i][d] = 0.f;
    }
    __syncthreads();

    const float SCALE = 0.08838834764831845f; // 1/sqrt(128)

    for (int kt = 0; kt <= qt; ++kt) {
        for (int i = tid; i < 64 * 32; i += 256) {
            int r = i >> 5, c = (i & 31) << 2;
            *(float4*)&Ks[r * 132 + c] =
                *(const float4*)(Kb + (size_t)(kt * 64 + r) * DIM + c);
            *(float4*)&Vs[r * 128 + c] =
                *(const float4*)(Vb + (size_t)(kt * 64 + r) * DIM + c);
        }
        __syncthreads();

        // S = Q K^T : thread handles q rows qr0..+3, k cols (tx + 16j)
        float s[4][4];
#pragma unroll
        for (int i = 0; i < 4; ++i)
#pragma unroll
            for (int j = 0; j < 4; ++j) s[i][j] = 0.f;

        for (int d0 = 0; d0 < HD; d0 += 4) {
            float4 kf[4];
#pragma unroll
            for (int j = 0; j < 4; ++j)
                kf[j] = *(const float4*)&Ks[(tx + 16 * j) * 132 + d0];
#pragma unroll
            for (int i = 0; i < 4; ++i) {
                float4 qf = *(const float4*)&Qs[(qr0 + i) * 128 + d0];
#pragma unroll
                for (int j = 0; j < 4; ++j) {
                    s[i][j] = fmaf(qf.x, kf[j].x, s[i][j]);
                    s[i][j] = fmaf(qf.y, kf[j].y, s[i][j]);
                    s[i][j] = fmaf(qf.z, kf[j].z, s[i][j]);
                    s[i][j] = fmaf(qf.w, kf[j].w, s[i][j]);
                }
            }
        }

#pragma unroll
        for (int i = 0; i < 4; ++i)
#pragma unroll
            for (int j = 0; j < 4; ++j) s[i][j] *= SCALE;

        if (kt == qt) {
#pragma unroll
            for (int i = 0; i < 4; ++i) {
                int qidx = qt * 64 + qr0 + i;
#pragma unroll
                for (int j = 0; j < 4; ++j) {
                    int kidx = kt * 64 + tx + 16 * j;
                    if (kidx > qidx) s[i][j] = -1e30f;
                }
            }
        }

        // online softmax per q row (reduce over the 16 tx lanes)
#pragma unroll
        for (int i = 0; i < 4; ++i) {
            float mr = fmaxf(fmaxf(s[i][0], s[i][1]), fmaxf(s[i][2], s[i][3]));
#pragma unroll
            for (int off = 1; off < 16; off <<= 1)
                mr = fmaxf(mr, __shfl_xor_sync(~0u, mr, off));
            float mn = fmaxf(m[i], mr);
            float corr = __expf(m[i] - mn);
            m[i] = mn;
            float p0 = __expf(s[i][0] - mn);
            float p1 = __expf(s[i][1] - mn);
            float p2 = __expf(s[i][2] - mn);
            float p3 = __expf(s[i][3] - mn);
            float ls = p0 + p1 + p2 + p3;
#pragma unroll
            for (int off = 1; off < 16; off <<= 1)
                ls += __shfl_xor_sync(~0u, ls, off);
            l[i] = l[i] * corr + ls;
#pragma unroll
            for (int d = 0; d < 8; ++d) o[i][d] *= corr;
            Ps[(qr0 + i) * 64 + tx]      = p0;
            Ps[(qr0 + i) * 64 + tx + 16] = p1;
            Ps[(qr0 + i) * 64 + tx + 32] = p2;
            Ps[(qr0 + i) * 64 + tx + 48] = p3;
        }
        __syncthreads();

        // O += P V
        for (int kk = 0; kk < 64; ++kk) {
            float4 v0 = *(const float4*)&Vs[kk * 128 + dc0];
            float4 v1 = *(const float4*)&Vs[kk * 128 + dc0 + 4];
#pragma unroll
            for (int i = 0; i < 4; ++i) {
                float p = Ps[(qr0 + i) * 64 + kk];
                o[i][0] = fmaf(p, v0.x, o[i][0]);
                o[i][1] = fmaf(p, v0.y, o[i][1]);
                o[i][2] = fmaf(p, v0.z, o[i][2]);
                o[i][3] = fmaf(p, v0.w, o[i][3]);
                o[i][4] = fmaf(p, v1.x, o[i][4]);
                o[i][5] = fmaf(p, v1.y, o[i][5]);
                o[i][6] = fmaf(p, v1.z, o[i][6]);
                o[i][7] = fmaf(p, v1.w, o[i][7]);
            }
        }
        __syncthreads();
    }

#pragma unroll
    for (int i = 0; i < 4; ++i) {
        float inv = 1.f / l[i];
        int row = qt * 64 + qr0 + i;
        float* op = O + (size_t)(b * SQ + row) * DIM + (size_t)h * HD + dc0;
        float4 r0 = make_float4(o[i][0] * inv, o[i][1] * inv, o[i][2] * inv, o[i][3] * inv);
        float4 r1 = make_float4(o[i][4] * inv, o[i][5] * inv, o[i][6] * inv, o[i][7] * inv);
        *(float4*)op       = r0;
        *(float4*)(op + 4) = r1;
    }
}

// ---------------- elementwise ----------------------------------------------
__global__ void add_kernel(const float* __restrict__ a, const float* __restrict__ b,
                           float* __restrict__ c, int n)
{
    int i = blockIdx.x * blockDim.x + threadIdx.x;
    if (i < n) c[i] = a[i] + b[i];
}

__global__ void diagG_kernel(const float* __restrict__ W, float* __restrict__ diag)
{
    int j = blockIdx.x * blockDim.x + threadIdx.x;
    if (j < DLCA) {
        float s = 0.f;
        for (int i = 0; i < DIM; ++i) {
            float w = W[(size_t)i * DLCA + j];
            s = fmaf(w, w, s);
        }
        diag[j] = s;
    }
}

__global__ void lca_init_kernel(const float* __restrict__ b, float* __restrict__ u,
                                float* __restrict__ a, int n)
{
    int i = blockIdx.x * blockDim.x + threadIdx.x;
    if (i < n) {
        float uv = 0.1f * b[i];        // u1 = u0 + (dt/tau)*(b - 0 - 0)
        u[i] = uv;
        a[i] = fmaxf(uv - 0.1f, 0.f);  // a = relu(u - lambda)
    }
}

__global__ void lca_update_kernel(float* __restrict__ u, float* __restrict__ a,
                                  const float* __restrict__ b, const float* __restrict__ t2,
                                  const float* __restrict__ diag, int n)
{
    int i = blockIdx.x * blockDim.x + threadIdx.x;
    if (i < n) {
        float av  = a[i];
        float inh = t2[i] - av * diag[i & (DLCA - 1)]; // a@G with zeroed diagonal
        float uv  = u[i];
        uv += 0.1f * (b[i] - inh - uv);                // dt/tau = 0.1
        u[i] = uv;
        a[i] = fmaxf(uv - 0.1f, 0.f);
    }
}

__global__ void silu_mul_kernel(float* __restrict__ g, const float* __restrict__ up, int n)
{
    int i = blockIdx.x * blockDim.x + threadIdx.x;
    if (i < n) {
        float x = g[i];
        float sig = 1.f / (1.f + expf(-x));
        g[i] = x * sig * up[i];
    }
}

// ---------------- launch ----------------------------------------------------
static inline float* devptr(float* p) { return p; }

extern "C" void kernel_launch(void* const* d_in, const int* in_sizes, int n_in,
                              void* d_out, int out_size)
{
    const float* x       = (const float*)d_in[0];
    const float* w_in    = (const float*)d_in[1];
    const float* w_lcaN  = (const float*)d_in[2];
    const float* w_post  = (const float*)d_in[3];
    const float* Wq      = (const float*)d_in[4];
    const float* Wk      = (const float*)d_in[5];
    const float* Wv      = (const float*)d_in[6];
    const float* Wo      = (const float*)d_in[7];
    const float* W_lca   = (const float*)d_in[8];
    const float* W_gate  = (const float*)d_in[9];
    const float* W_up    = (const float*)d_in[10];
    const float* W_down  = (const float*)d_in[11];
    float* out = (float*)d_out;

    float *hn, *q, *k, *v, *attn, *ao, *h, *t1, *mlp, *b, *u, *a, *t2, *gate, *up, *diag;
    cudaGetSymbolAddress((void**)&hn,   g_hn);
    cudaGetSymbolAddress((void**)&q,    g_q);
    cudaGetSymbolAddress((void**)&k,    g_k);
    cudaGetSymbolAddress((void**)&v,    g_v);
    cudaGetSymbolAddress((void**)&attn, g_attn);
    cudaGetSymbolAddress((void**)&ao,   g_ao);
    cudaGetSymbolAddress((void**)&h,    g_h);
    cudaGetSymbolAddress((void**)&t1,   g_t1);
    cudaGetSymbolAddress((void**)&mlp,  g_mlp);
    cudaGetSymbolAddress((void**)&b,    g_b);
    cudaGetSymbolAddress((void**)&u,    g_u);
    cudaGetSymbolAddress((void**)&a,    g_a);
    cudaGetSymbolAddress((void**)&t2,   g_t2);
    cudaGetSymbolAddress((void**)&gate, g_gate);
    cudaGetSymbolAddress((void**)&up,   g_up);
    cudaGetSymbolAddress((void**)&diag, g_diag);

    cudaFuncSetAttribute(attn_kernel,
                         cudaFuncAttributeMaxDynamicSharedMemorySize, ATTN_SMEM_BYTES);

    const int ND  = NROWS * DIM;    // 8.4M
    const int NL  = NROWS * DLCA;   // 16.8M
    const int NF  = NROWS * DFF;    // 33.5M
    dim3 gD(DIM  / BN, NROWS / BM); // (16,32)
    dim3 gL(DLCA / BN, NROWS / BM); // (32,32)
    dim3 gF(DFF  / BN, NROWS / BM); // (64,32)

    // ---- attention block ----
    rmsnorm_kernel<<<NROWS, 256>>>(x, w_in, hn);
    sgemm_nn<<<gD, 256>>>(hn, Wq, q, NROWS, DIM, DIM);
    sgemm_nn<<<gD, 256>>>(hn, Wk, k, NROWS, DIM, DIM);
    sgemm_nn<<<gD, 256>>>(hn, Wv, v, NROWS, DIM, DIM);
    rope_kernel<<<(NROWS * NH * 64 + 255) / 256, 256>>>(q, k);
    attn_kernel<<<dim3(SQ / 64, NH, BATCH), 256, ATTN_SMEM_BYTES>>>(q, k, v, attn);
    sgemm_nn<<<gD, 256>>>(attn, Wo, ao, NROWS, DIM, DIM);
    add_kernel<<<(ND + 255) / 256, 256>>>(x, ao, h, ND);

    // ---- LCA block ----
    rmsnorm_kernel<<<NROWS, 256>>>(h, w_lcaN, hn);
    sgemm_nn<<<gL, 256>>>(hn, W_lca, b, NROWS, DLCA, DIM);
    diagG_kernel<<<DLCA / 256, 256>>>(W_lca, diag);
    lca_init_kernel<<<(NL + 255) / 256, 256>>>(b, u, a, NL);
    for (int it = 0; it < 9; ++it) {
        sgemm_nt<<<gD, 256>>>(a, W_lca, t1, NROWS, DIM, DLCA);   // a @ W^T
        sgemm_nn<<<gL, 256>>>(t1, W_lca, t2, NROWS, DLCA, DIM);  // (a@W^T) @ W
        lca_update_kernel<<<(NL + 255) / 256, 256>>>(u, a, b, t2, diag, NL);
    }
    sgemm_nt<<<gD, 256>>>(a, W_lca, h, NROWS, DIM, DLCA);        // h = a @ W^T (replaces stream)

    // ---- MLP block ----
    rmsnorm_kernel<<<NROWS, 256>>>(h, w_post, hn);
    sgemm_nn<<<gF, 256>>>(hn, W_gate, gate, NROWS, DFF, DIM);
    sgemm_nn<<<gF, 256>>>(hn, W_up,   up,   NROWS, DFF, DIM);
    silu_mul_kernel<<<(NF + 255) / 256, 256>>>(gate, up, NF);
    sgemm_nn<<<gD, 256>>>(gate, W_down, mlp, NROWS, DIM, DFF);
    add_kernel<<<(ND + 255) / 256, 256>>>(h, mlp, out, ND);
}

// round 3
// speedup vs baseline: 2.9995x; 2.9995x over previous
#include <cuda_runtime.h>
#include <math.h>

#define SQ    2048
#define DIM   2048
#define NH    16
#define HD    128
#define BATCH 2
#define NROWS 4096      // B*S
#define DLCA  4096
#define DFF   8192

// ---------------- scratch (static device globals; no allocs allowed) -------
__device__ float g_hn  [(size_t)NROWS*DIM];
__device__ float g_q   [(size_t)NROWS*DIM];
__device__ float g_k   [(size_t)NROWS*DIM];
__device__ float g_v   [(size_t)NROWS*DIM];
__device__ float g_attn[(size_t)NROWS*DIM];
__device__ float g_ao  [(size_t)NROWS*DIM];
__device__ float g_h   [(size_t)NROWS*DIM];
__device__ float g_t1  [(size_t)NROWS*DIM];
__device__ float g_mlp [(size_t)NROWS*DIM];
__device__ float g_b   [(size_t)NROWS*DLCA];
__device__ float g_u   [(size_t)NROWS*DLCA];
__device__ float g_a   [(size_t)NROWS*DLCA];
__device__ float g_t2  [(size_t)NROWS*DLCA];
__device__ float g_gate[(size_t)NROWS*DFF];
__device__ float g_up  [(size_t)NROWS*DFF];
__device__ float g_diag[DLCA];

// ================= TF32 tensor-core GEMM =================
// C[M,N] = A[M,K] @ B, block tile 128x128x16, 8 warps (2m x 4n), warp tile 64x32,
// mma.sync.m16n8k8.tf32, cp.async double-buffered smem.

#define BM 128
#define BN 128
#define BK 16
#define AS_STRIDE 20            // 16 + 4 pad
#define BS_STRIDE 136           // 128 + 8 pad (nn B tile)
#define ASZ (BM * AS_STRIDE)    // 2560 floats
#define BSZ_NN (BK * BS_STRIDE) // 2176 floats
#define BSZ_NT (BN * AS_STRIDE) // 2560 floats

#define CP_ASYNC16(dst, src) \
    asm volatile("cp.async.cg.shared.global [%0], [%1], 16;\n" :: "r"(dst), "l"(src))
#define CP_COMMIT() asm volatile("cp.async.commit_group;\n")
#define CP_WAIT0()  asm volatile("cp.async.wait_group 0;\n" ::: "memory")

__device__ __forceinline__ unsigned f2tf32(float f) {
    unsigned r;
    asm("cvt.rna.tf32.f32 %0, %1;" : "=r"(r) : "f"(f));
    return r;
}

#define MMA_TF32(c, a, b) \
    asm volatile("mma.sync.aligned.m16n8k8.row.col.f32.tf32.tf32.f32 " \
                 "{%0,%1,%2,%3}, {%4,%5,%6,%7}, {%8,%9}, {%0,%1,%2,%3};" \
                 : "+f"((c)[0]), "+f"((c)[1]), "+f"((c)[2]), "+f"((c)[3]) \
                 : "r"((a)[0]), "r"((a)[1]), "r"((a)[2]), "r"((a)[3]), \
                   "r"((b)[0]), "r"((b)[1]))

// ---- NN: B is [K,N] row-major ----
__global__ __launch_bounds__(256, 2) void mma_gemm_nn(
    const float* __restrict__ A, const float* __restrict__ B, float* __restrict__ C,
    int M, int N, int K)
{
    __shared__ __align__(16) float sm[2 * (ASZ + BSZ_NN)];
    const int STAGE = ASZ + BSZ_NN;

    int tid = threadIdx.x;
    int bx = blockIdx.x, by = blockIdx.y;
    int warp = tid >> 5, lane = tid & 31;
    int wm = warp & 1, wn = warp >> 1;      // 2 x 4 warp grid
    int g = lane >> 2, q = lane & 3;

    const float* Ab = A + (size_t)by * BM * K;
    const float* Bb = B + (size_t)bx * BN;

    int ar = tid >> 2;          // 0..63
    int ac = (tid & 3) << 2;    // 0,4,8,12
    int br = tid >> 5;          // 0..7
    int bc = (tid & 31) << 2;   // 0..124

    unsigned smBase = (unsigned)__cvta_generic_to_shared(sm);

    float c[4][4][4];
#pragma unroll
    for (int i = 0; i < 4; ++i)
#pragma unroll
        for (int j = 0; j < 4; ++j)
#pragma unroll
            for (int r = 0; r < 4; ++r) c[i][j][r] = 0.f;

    int nTiles = K / BK;

    // prologue: prefetch tile 0 into stage 0
    {
        unsigned base = smBase;
        const float* ap = Ab + (size_t)ar * K + ac;
        CP_ASYNC16(base + (unsigned)(ar * AS_STRIDE + ac) * 4, ap);
        CP_ASYNC16(base + (unsigned)((ar + 64) * AS_STRIDE + ac) * 4, ap + (size_t)64 * K);
        unsigned bbase = base + ASZ * 4;
        const float* bp = Bb + (size_t)br * N + bc;
        CP_ASYNC16(bbase + (unsigned)(br * BS_STRIDE + bc) * 4, bp);
        CP_ASYNC16(bbase + (unsigned)((br + 8) * BS_STRIDE + bc) * 4, bp + (size_t)8 * N);
        CP_COMMIT();
    }

    for (int t = 0; t < nTiles; ++t) {
        int stage = t & 1;
        CP_WAIT0();
        __syncthreads();

        if (t + 1 < nTiles) {
            unsigned base = smBase + (unsigned)((stage ^ 1) * STAGE) * 4;
            const float* ap = Ab + (size_t)ar * K + (t + 1) * BK + ac;
            CP_ASYNC16(base + (unsigned)(ar * AS_STRIDE + ac) * 4, ap);
            CP_ASYNC16(base + (unsigned)((ar + 64) * AS_STRIDE + ac) * 4, ap + (size_t)64 * K);
            unsigned bbase = base + ASZ * 4;
            const float* bp = Bb + (size_t)((t + 1) * BK + br) * N + bc;
            CP_ASYNC16(bbase + (unsigned)(br * BS_STRIDE + bc) * 4, bp);
            CP_ASYNC16(bbase + (unsigned)((br + 8) * BS_STRIDE + bc) * 4, bp + (size_t)8 * N);
            CP_COMMIT();
        }

        const float* As = sm + stage * STAGE;
        const float* Bs = As + ASZ;

#pragma unroll
        for (int ks = 0; ks < BK; ks += 8) {
            unsigned a[4][4], b[4][2];
#pragma unroll
            for (int mi = 0; mi < 4; ++mi) {
                int row = wm * 64 + mi * 16 + g;
                a[mi][0] = f2tf32(As[row * AS_STRIDE + ks + q]);
                a[mi][1] = f2tf32(As[(row + 8) * AS_STRIDE + ks + q]);
                a[mi][2] = f2tf32(As[row * AS_STRIDE + ks + q + 4]);
                a[mi][3] = f2tf32(As[(row + 8) * AS_STRIDE + ks + q + 4]);
            }
#pragma unroll
            for (int ni = 0; ni < 4; ++ni) {
                int col = wn * 32 + ni * 8 + g;
                b[ni][0] = f2tf32(Bs[(ks + q) * BS_STRIDE + col]);
                b[ni][1] = f2tf32(Bs[(ks + q + 4) * BS_STRIDE + col]);
            }
#pragma unroll
            for (int mi = 0; mi < 4; ++mi)
#pragma unroll
                for (int ni = 0; ni < 4; ++ni)
                    MMA_TF32(c[mi][ni], a[mi], b[ni]);
        }
        __syncthreads();
    }

    // epilogue
#pragma unroll
    for (int mi = 0; mi < 4; ++mi) {
        int row0 = by * BM + wm * 64 + mi * 16 + g;
#pragma unroll
        for (int ni = 0; ni < 4; ++ni) {
            int col = bx * BN + wn * 32 + ni * 8 + q * 2;
            *(float2*)(C + (size_t)row0 * N + col) = make_float2(c[mi][ni][0], c[mi][ni][1]);
            *(float2*)(C + (size_t)(row0 + 8) * N + col) = make_float2(c[mi][ni][2], c[mi][ni][3]);
        }
    }
}

// ---- NT: C = A[M,K] @ Bt[N,K]^T ----
__global__ __launch_bounds__(256, 2) void mma_gemm_nt(
    const float* __restrict__ A, const float* __restrict__ Bt, float* __restrict__ C,
    int M, int N, int K)
{
    __shared__ __align__(16) float sm[2 * (ASZ + BSZ_NT)];
    const int STAGE = ASZ + BSZ_NT;

    int tid = threadIdx.x;
    int bx = blockIdx.x, by = blockIdx.y;
    int warp = tid >> 5, lane = tid & 31;
    int wm = warp & 1, wn = warp >> 1;
    int g = lane >> 2, q = lane & 3;

    const float* Ab = A  + (size_t)by * BM * K;
    const float* Bb = Bt + (size_t)bx * BN * K;

    int ar = tid >> 2;          // 0..63
    int ac = (tid & 3) << 2;    // 0,4,8,12

    unsigned smBase = (unsigned)__cvta_generic_to_shared(sm);

    float c[4][4][4];
#pragma unroll
    for (int i = 0; i < 4; ++i)
#pragma unroll
        for (int j = 0; j < 4; ++j)
#pragma unroll
            for (int r = 0; r < 4; ++r) c[i][j][r] = 0.f;

    int nTiles = K / BK;

    {
        unsigned base = smBase;
        const float* ap = Ab + (size_t)ar * K + ac;
        CP_ASYNC16(base + (unsigned)(ar * AS_STRIDE + ac) * 4, ap);
        CP_ASYNC16(base + (unsigned)((ar + 64) * AS_STRIDE + ac) * 4, ap + (size_t)64 * K);
        unsigned bbase = base + ASZ * 4;
        const float* bp = Bb + (size_t)ar * K + ac;
        CP_ASYNC16(bbase + (unsigned)(ar * AS_STRIDE + ac) * 4, bp);
        CP_ASYNC16(bbase + (unsigned)((ar + 64) * AS_STRIDE + ac) * 4, bp + (size_t)64 * K);
        CP_COMMIT();
    }

    for (int t = 0; t < nTiles; ++t) {
        int stage = t & 1;
        CP_WAIT0();
        __syncthreads();

        if (t + 1 < nTiles) {
            unsigned base = smBase + (unsigned)((stage ^ 1) * STAGE) * 4;
            const float* ap = Ab + (size_t)ar * K + (t + 1) * BK + ac;
            CP_ASYNC16(base + (unsigned)(ar * AS_STRIDE + ac) * 4, ap);
            CP_ASYNC16(base + (unsigned)((ar + 64) * AS_STRIDE + ac) * 4, ap + (size_t)64 * K);
            unsigned bbase = base + ASZ * 4;
            const float* bp = Bb + (size_t)ar * K + (t + 1) * BK + ac;
            CP_ASYNC16(bbase + (unsigned)(ar * AS_STRIDE + ac) * 4, bp);
            CP_ASYNC16(bbase + (unsigned)((ar + 64) * AS_STRIDE + ac) * 4, bp + (size_t)64 * K);
            CP_COMMIT();
        }

        const float* As = sm + stage * STAGE;
        const float* Bs = As + ASZ;   // [BN][AS_STRIDE], n-major

#pragma unroll
        for (int ks = 0; ks < BK; ks += 8) {
            unsigned a[4][4], b[4][2];
#pragma unroll
            for (int mi = 0; mi < 4; ++mi) {
                int row = wm * 64 + mi * 16 + g;
                a[mi][0] = f2tf32(As[row * AS_STRIDE + ks + q]);
                a[mi][1] = f2tf32(As[(row + 8) * AS_STRIDE + ks + q]);
                a[mi][2] = f2tf32(As[row * AS_STRIDE + ks + q + 4]);
                a[mi][3] = f2tf32(As[(row + 8) * AS_STRIDE + ks + q + 4]);
            }
#pragma unroll
            for (int ni = 0; ni < 4; ++ni) {
                int col = wn * 32 + ni * 8 + g;
                b[ni][0] = f2tf32(Bs[col * AS_STRIDE + ks + q]);
                b[ni][1] = f2tf32(Bs[col * AS_STRIDE + ks + q + 4]);
            }
#pragma unroll
            for (int mi = 0; mi < 4; ++mi)
#pragma unroll
                for (int ni = 0; ni < 4; ++ni)
                    MMA_TF32(c[mi][ni], a[mi], b[ni]);
        }
        __syncthreads();
    }

#pragma unroll
    for (int mi = 0; mi < 4; ++mi) {
        int row0 = by * BM + wm * 64 + mi * 16 + g;
#pragma unroll
        for (int ni = 0; ni < 4; ++ni) {
            int col = bx * BN + wn * 32 + ni * 8 + q * 2;
            *(float2*)(C + (size_t)row0 * N + col) = make_float2(c[mi][ni][0], c[mi][ni][1]);
            *(float2*)(C + (size_t)(row0 + 8) * N + col) = make_float2(c[mi][ni][2], c[mi][ni][3]);
        }
    }
}

// ---------------- RMSNorm ---------------------------------------------------
__global__ __launch_bounds__(256) void rmsnorm_kernel(
    const float* __restrict__ x, const float* __restrict__ w, float* __restrict__ out)
{
    __shared__ float red[8];
    int row = blockIdx.x, tid = threadIdx.x;
    const float* xr = x + (size_t)row * DIM;
    float4 v[2];
    float ss = 0.f;
#pragma unroll
    for (int p = 0; p < 2; ++p) {
        v[p] = *(const float4*)(xr + p * 1024 + tid * 4);
        ss += v[p].x * v[p].x + v[p].y * v[p].y + v[p].z * v[p].z + v[p].w * v[p].w;
    }
#pragma unroll
    for (int off = 16; off; off >>= 1) ss += __shfl_xor_sync(~0u, ss, off);
    if ((tid & 31) == 0) red[tid >> 5] = ss;
    __syncthreads();
    if (tid == 0) {
        float t = 0.f;
#pragma unroll
        for (int i = 0; i < 8; ++i) t += red[i];
        red[0] = rsqrtf(t / (float)DIM + 1e-6f);
    }
    __syncthreads();
    float inv = red[0];
    float* orow = out + (size_t)row * DIM;
#pragma unroll
    for (int p = 0; p < 2; ++p) {
        int cix = p * 1024 + tid * 4;
        float4 wv = *(const float4*)(w + cix);
        float4 o;
        o.x = v[p].x * inv * wv.x; o.y = v[p].y * inv * wv.y;
        o.z = v[p].z * inv * wv.z; o.w = v[p].w * inv * wv.w;
        *(float4*)(orow + cix) = o;
    }
}

// ---------------- RoPE (in-place on q and k) --------------------------------
__global__ void rope_kernel(float* __restrict__ q, float* __restrict__ k)
{
    int idx = blockIdx.x * blockDim.x + threadIdx.x;
    if (idx >= NROWS * NH * 64) return;
    int i   = idx & 63;
    int h   = (idx >> 6) & (NH - 1);
    int row = idx >> 10;
    int pos = row & (SQ - 1);
    float inv = (float)exp(-((double)(2 * i) / (double)HD) * 9.210340371976184); // ln(1e4)
    float ang = (float)pos * inv;
    float sn, cs;
    sincosf(ang, &sn, &cs);
    size_t base = (size_t)row * DIM + (size_t)h * HD;
    float a = q[base + i], b = q[base + i + 64];
    q[base + i]      = a * cs - b * sn;
    q[base + i + 64] = b * cs + a * sn;
    a = k[base + i]; b = k[base + i + 64];
    k[base + i]      = a * cs - b * sn;
    k[base + i + 64] = b * cs + a * sn;
}

// ---------------- Flash attention (causal), 64x64 tiles ---------------------
#define ATTN_SMEM_FLOATS (64*128 + 64*132 + 64*128 + 64*64)
#define ATTN_SMEM_BYTES  (ATTN_SMEM_FLOATS * 4)

__global__ __launch_bounds__(256) void attn_kernel(
    const float* __restrict__ Q, const float* __restrict__ K,
    const float* __restrict__ V, float* __restrict__ O)
{
    extern __shared__ float smf[];
    float* Qs = smf;
    float* Ks = smf + 8192;
    float* Vs = smf + 8192 + 8448;
    float* Ps = smf + 8192 + 8448 + 8192;

    int qt = blockIdx.x, h = blockIdx.y, b = blockIdx.z;
    int tid = threadIdx.x;
    int ty = tid >> 4, tx = tid & 15;
    int qr0 = ty * 4;
    int dc0 = tx * 8;

    const float* Qb = Q + (size_t)b * SQ * DIM + (size_t)h * HD;
    const float* Kb = K + (size_t)b * SQ * DIM + (size_t)h * HD;
    const float* Vb = V + (size_t)b * SQ * DIM + (size_t)h * HD;

    for (int i = tid; i < 64 * 32; i += 256) {
        int r = i >> 5, cix = (i & 31) << 2;
        *(float4*)&Qs[r * 128 + cix] =
            *(const float4*)(Qb + (size_t)(qt * 64 + r) * DIM + cix);
    }

    float m[4], l[4], o[4][8];
#pragma unroll
    for (int i = 0; i < 4; ++i) {
        m[i] = -3.0e38f; l[i] = 0.f;
#pragma unroll
        for (int d = 0; d < 8; ++d) o[i][d] = 0.f;
    }
    __syncthreads();

    const float SCALE = 0.08838834764831845f;

    for (int kt = 0; kt <= qt; ++kt) {
        for (int i = tid; i < 64 * 32; i += 256) {
            int r = i >> 5, cix = (i & 31) << 2;
            *(float4*)&Ks[r * 132 + cix] =
                *(const float4*)(Kb + (size_t)(kt * 64 + r) * DIM + cix);
            *(float4*)&Vs[r * 128 + cix] =
                *(const float4*)(Vb + (size_t)(kt * 64 + r) * DIM + cix);
        }
        __syncthreads();

        float s[4][4];
#pragma unroll
        for (int i = 0; i < 4; ++i)
#pragma unroll
            for (int j = 0; j < 4; ++j) s[i][j] = 0.f;

        for (int d0 = 0; d0 < HD; d0 += 4) {
            float4 kf[4];
#pragma unroll
            for (int j = 0; j < 4; ++j)
                kf[j] = *(const float4*)&Ks[(tx + 16 * j) * 132 + d0];
#pragma unroll
            for (int i = 0; i < 4; ++i) {
                float4 qf = *(const float4*)&Qs[(qr0 + i) * 128 + d0];
#pragma unroll
                for (int j = 0; j < 4; ++j) {
                    s[i][j] = fmaf(qf.x, kf[j].x, s[i][j]);
                    s[i][j] = fmaf(qf.y, kf[j].y, s[i][j]);
                    s[i][j] = fmaf(qf.z, kf[j].z, s[i][j]);
                    s[i][j] = fmaf(qf.w, kf[j].w, s[i][j]);
                }
            }
        }

#pragma unroll
        for (int i = 0; i < 4; ++i)
#pragma unroll
            for (int j = 0; j < 4; ++j) s[i][j] *= SCALE;

        if (kt == qt) {
#pragma unroll
            for (int i = 0; i < 4; ++i) {
                int qidx = qt * 64 + qr0 + i;
#pragma unroll
                for (int j = 0; j < 4; ++j) {
                    int kidx = kt * 64 + tx + 16 * j;
                    if (kidx > qidx) s[i][j] = -1e30f;
                }
            }
        }

#pragma unroll
        for (int i = 0; i < 4; ++i) {
            float mr = fmaxf(fmaxf(s[i][0], s[i][1]), fmaxf(s[i][2], s[i][3]));
#pragma unroll
            for (int off = 1; off < 16; off <<= 1)
                mr = fmaxf(mr, __shfl_xor_sync(~0u, mr, off));
            float mn = fmaxf(m[i], mr);
            float corr = __expf(m[i] - mn);
            m[i] = mn;
            float p0 = __expf(s[i][0] - mn);
            float p1 = __expf(s[i][1] - mn);
            float p2 = __expf(s[i][2] - mn);
            float p3 = __expf(s[i][3] - mn);
            float ls = p0 + p1 + p2 + p3;
#pragma unroll
            for (int off = 1; off < 16; off <<= 1)
                ls += __shfl_xor_sync(~0u, ls, off);
            l[i] = l[i] * corr + ls;
#pragma unroll
            for (int d = 0; d < 8; ++d) o[i][d] *= corr;
            Ps[(qr0 + i) * 64 + tx]      = p0;
            Ps[(qr0 + i) * 64 + tx + 16] = p1;
            Ps[(qr0 + i) * 64 + tx + 32] = p2;
            Ps[(qr0 + i) * 64 + tx + 48] = p3;
        }
        __syncthreads();

        for (int kk = 0; kk < 64; ++kk) {
            float4 v0 = *(const float4*)&Vs[kk * 128 + dc0];
            float4 v1 = *(const float4*)&Vs[kk * 128 + dc0 + 4];
#pragma unroll
            for (int i = 0; i < 4; ++i) {
                float p = Ps[(qr0 + i) * 64 + kk];
                o[i][0] = fmaf(p, v0.x, o[i][0]);
                o[i][1] = fmaf(p, v0.y, o[i][1]);
                o[i][2] = fmaf(p, v0.z, o[i][2]);
                o[i][3] = fmaf(p, v0.w, o[i][3]);
                o[i][4] = fmaf(p, v1.x, o[i][4]);
                o[i][5] = fmaf(p, v1.y, o[i][5]);
                o[i][6] = fmaf(p, v1.z, o[i][6]);
                o[i][7] = fmaf(p, v1.w, o[i][7]);
            }
        }
        __syncthreads();
    }

#pragma unroll
    for (int i = 0; i < 4; ++i) {
        float inv = 1.f / l[i];
        int row = qt * 64 + qr0 + i;
        float* op = O + (size_t)(b * SQ + row) * DIM + (size_t)h * HD + dc0;
        float4 r0 = make_float4(o[i][0] * inv, o[i][1] * inv, o[i][2] * inv, o[i][3] * inv);
        float4 r1 = make_float4(o[i][4] * inv, o[i][5] * inv, o[i][6] * inv, o[i][7] * inv);
        *(float4*)op       = r0;
        *(float4*)(op + 4) = r1;
    }
}

// ---------------- elementwise ----------------------------------------------
__global__ void add_kernel(const float* __restrict__ a, const float* __restrict__ b,
                           float* __restrict__ c, int n)
{
    int i = blockIdx.x * blockDim.x + threadIdx.x;
    if (i < n) c[i] = a[i] + b[i];
}

__global__ void diagG_kernel(const float* __restrict__ W, float* __restrict__ diag)
{
    int j = blockIdx.x * blockDim.x + threadIdx.x;
    if (j < DLCA) {
        float s = 0.f;
        for (int i = 0; i < DIM; ++i) {
            float w = W[(size_t)i * DLCA + j];
            s = fmaf(w, w, s);
        }
        diag[j] = s;
    }
}

__global__ void lca_init_kernel(const float* __restrict__ b, float* __restrict__ u,
                                float* __restrict__ a, int n)
{
    int i = blockIdx.x * blockDim.x + threadIdx.x;
    if (i < n) {
        float uv = 0.1f * b[i];
        u[i] = uv;
        a[i] = fmaxf(uv - 0.1f, 0.f);
    }
}

__global__ void lca_update_kernel(float* __restrict__ u, float* __restrict__ a,
                                  const float* __restrict__ b, const float* __restrict__ t2,
                                  const float* __restrict__ diag, int n)
{
    int i = blockIdx.x * blockDim.x + threadIdx.x;
    if (i < n) {
        float av  = a[i];
        float inh = t2[i] - av * diag[i & (DLCA - 1)];
        float uv  = u[i];
        uv += 0.1f * (b[i] - inh - uv);
        u[i] = uv;
        a[i] = fmaxf(uv - 0.1f, 0.f);
    }
}

__global__ void silu_mul_kernel(float* __restrict__ g, const float* __restrict__ up, int n)
{
    int i = blockIdx.x * blockDim.x + threadIdx.x;
    if (i < n) {
        float x = g[i];
        float sig = 1.f / (1.f + expf(-x));
        g[i] = x * sig * up[i];
    }
}

// ---------------- launch ----------------------------------------------------
extern "C" void kernel_launch(void* const* d_in, const int* in_sizes, int n_in,
                              void* d_out, int out_size)
{
    const float* x       = (const float*)d_in[0];
    const float* w_in    = (const float*)d_in[1];
    const float* w_lcaN  = (const float*)d_in[2];
    const float* w_post  = (const float*)d_in[3];
    const float* Wq      = (const float*)d_in[4];
    const float* Wk      = (const float*)d_in[5];
    const float* Wv      = (const float*)d_in[6];
    const float* Wo      = (const float*)d_in[7];
    const float* W_lca   = (const float*)d_in[8];
    const float* W_gate  = (const float*)d_in[9];
    const float* W_up    = (const float*)d_in[10];
    const float* W_down  = (const float*)d_in[11];
    float* out = (float*)d_out;

    float *hn, *q, *k, *v, *attn, *ao, *h, *t1, *mlp, *b, *u, *a, *t2, *gate, *up, *diag;
    cudaGetSymbolAddress((void**)&hn,   g_hn);
    cudaGetSymbolAddress((void**)&q,    g_q);
    cudaGetSymbolAddress((void**)&k,    g_k);
    cudaGetSymbolAddress((void**)&v,    g_v);
    cudaGetSymbolAddress((void**)&attn, g_attn);
    cudaGetSymbolAddress((void**)&ao,   g_ao);
    cudaGetSymbolAddress((void**)&h,    g_h);
    cudaGetSymbolAddress((void**)&t1,   g_t1);
    cudaGetSymbolAddress((void**)&mlp,  g_mlp);
    cudaGetSymbolAddress((void**)&b,    g_b);
    cudaGetSymbolAddress((void**)&u,    g_u);
    cudaGetSymbolAddress((void**)&a,    g_a);
    cudaGetSymbolAddress((void**)&t2,   g_t2);
    cudaGetSymbolAddress((void**)&gate, g_gate);
    cudaGetSymbolAddress((void**)&up,   g_up);
    cudaGetSymbolAddress((void**)&diag, g_diag);

    cudaFuncSetAttribute(attn_kernel,
                         cudaFuncAttributeMaxDynamicSharedMemorySize, ATTN_SMEM_BYTES);

    const int ND  = NROWS * DIM;
    const int NL  = NROWS * DLCA;
    const int NF  = NROWS * DFF;
    dim3 gD(DIM  / BN, NROWS / BM);
    dim3 gL(DLCA / BN, NROWS / BM);
    dim3 gF(DFF  / BN, NROWS / BM);

    // ---- attention block ----
    rmsnorm_kernel<<<NROWS, 256>>>(x, w_in, hn);
    mma_gemm_nn<<<gD, 256>>>(hn, Wq, q, NROWS, DIM, DIM);
    mma_gemm_nn<<<gD, 256>>>(hn, Wk, k, NROWS, DIM, DIM);
    mma_gemm_nn<<<gD, 256>>>(hn, Wv, v, NROWS, DIM, DIM);
    rope_kernel<<<(NROWS * NH * 64 + 255) / 256, 256>>>(q, k);
    attn_kernel<<<dim3(SQ / 64, NH, BATCH), 256, ATTN_SMEM_BYTES>>>(q, k, v, attn);
    mma_gemm_nn<<<gD, 256>>>(attn, Wo, ao, NROWS, DIM, DIM);
    add_kernel<<<(ND + 255) / 256, 256>>>(x, ao, h, ND);

    // ---- LCA block ----
    rmsnorm_kernel<<<NROWS, 256>>>(h, w_lcaN, hn);
    mma_gemm_nn<<<gL, 256>>>(hn, W_lca, b, NROWS, DLCA, DIM);
    diagG_kernel<<<DLCA / 256, 256>>>(W_lca, diag);
    lca_init_kernel<<<(NL + 255) / 256, 256>>>(b, u, a, NL);
    for (int it = 0; it < 9; ++it) {
        mma_gemm_nt<<<gD, 256>>>(a, W_lca, t1, NROWS, DIM, DLCA);   // a @ W^T
        mma_gemm_nn<<<gL, 256>>>(t1, W_lca, t2, NROWS, DLCA, DIM);  // (a@W^T) @ W
        lca_update_kernel<<<(NL + 255) / 256, 256>>>(u, a, b, t2, diag, NL);
    }
    mma_gemm_nt<<<gD, 256>>>(a, W_lca, h, NROWS, DIM, DLCA);        // h = a @ W^T

    // ---- MLP block ----
    rmsnorm_kernel<<<NROWS, 256>>>(h, w_post, hn);
    mma_gemm_nn<<<gF, 256>>>(hn, W_gate, gate, NROWS, DFF, DIM);
    mma_gemm_nn<<<gF, 256>>>(hn, W_up,   up,   NROWS, DFF, DIM);
    silu_mul_kernel<<<(NF + 255) / 256, 256>>>(gate, up, NF);
    mma_gemm_nn<<<gD, 256>>>(gate, W_down, mlp, NROWS, DIM, DFF);
    add_kernel<<<(ND + 255) / 256, 256>>>(h, mlp, out, ND);
}

// round 4
// speedup vs baseline: 3.4587x; 1.1531x over previous
#include <cuda_runtime.h>
#include <math.h>

#define SQ    2048
#define DIM   2048
#define NH    16
#define HD    128
#define BATCH 2
#define NROWS 4096      // B*S
#define DLCA  4096
#define DFF   8192

// ---------------- scratch (static device globals; no allocs allowed) -------
__device__ float g_hn  [(size_t)NROWS*DIM];
__device__ float g_q   [(size_t)NROWS*DIM];
__device__ float g_k   [(size_t)NROWS*DIM];
__device__ float g_v   [(size_t)NROWS*DIM];
__device__ float g_attn[(size_t)NROWS*DIM];
__device__ float g_ao  [(size_t)NROWS*DIM];
__device__ float g_h   [(size_t)NROWS*DIM];
__device__ float g_t1  [(size_t)NROWS*DIM];
__device__ float g_mlp [(size_t)NROWS*DIM];
__device__ float g_b   [(size_t)NROWS*DLCA];
__device__ float g_u   [(size_t)NROWS*DLCA];
__device__ float g_a   [(size_t)NROWS*DLCA];
__device__ float g_t2  [(size_t)NROWS*DLCA];
__device__ float g_gate[(size_t)NROWS*DFF];
__device__ float g_up  [(size_t)NROWS*DFF];
__device__ float g_diag[DLCA];
// tf32-rounded weight copies
__device__ float g_wq   [(size_t)DIM*DIM];
__device__ float g_wk   [(size_t)DIM*DIM];
__device__ float g_wv   [(size_t)DIM*DIM];
__device__ float g_wo   [(size_t)DIM*DIM];
__device__ float g_wlca [(size_t)DIM*DLCA];
__device__ float g_wgate[(size_t)DIM*DFF];
__device__ float g_wup  [(size_t)DIM*DFF];
__device__ float g_wdown[(size_t)DFF*DIM];

// ---------------- tf32 helpers ---------------------------------------------
__device__ __forceinline__ unsigned f2tf32(float f) {
    unsigned r;
    asm("cvt.rna.tf32.f32 %0, %1;" : "=r"(r) : "f"(f));
    return r;
}
__device__ __forceinline__ float rtf32(float f) { return __uint_as_float(f2tf32(f)); }

#define CP_ASYNC16(dst, src) \
    asm volatile("cp.async.cg.shared.global [%0], [%1], 16;\n" :: "r"(dst), "l"(src))
#define CP_COMMIT() asm volatile("cp.async.commit_group;\n")
#define CP_WAIT1()  asm volatile("cp.async.wait_group 1;\n" ::: "memory")

#define MMA_TF32(c, a, b) \
    asm volatile("mma.sync.aligned.m16n8k8.row.col.f32.tf32.tf32.f32 " \
                 "{%0,%1,%2,%3}, {%4,%5,%6,%7}, {%8,%9}, {%0,%1,%2,%3};" \
                 : "+f"((c)[0]), "+f"((c)[1]), "+f"((c)[2]), "+f"((c)[3]) \
                 : "r"((a)[0]), "r"((a)[1]), "r"((a)[2]), "r"((a)[3]), \
                   "r"((b)[0]), "r"((b)[1]))

// ================= TF32 tensor-core GEMM (operands pre-rounded) ============
#define BM 128
#define BN 128
#define BK 16
#define AS_STRIDE 20            // 16 + 4 pad
#define BS_STRIDE 136           // 128 + 8 pad (nn B tile)
#define ASZ (BM * AS_STRIDE)    // 2560 floats
#define BSZ_NN (BK * BS_STRIDE) // 2176 floats
#define BSZ_NT (BN * AS_STRIDE) // 2560 floats
#define NN_STAGE (ASZ + BSZ_NN) // 4736 floats
#define NT_STAGE (ASZ + BSZ_NT) // 5120 floats
#define NN_SMEM_BYTES (3 * NN_STAGE * 4)
#define NT_SMEM_BYTES (3 * NT_STAGE * 4)

// ---- NN: C[M,N] = A[M,K] @ B[K,N] ----
template<bool RC>
__global__ __launch_bounds__(256, 2) void mma_gemm_nn(
    const float* __restrict__ A, const float* __restrict__ B, float* __restrict__ C,
    int M, int N, int K)
{
    extern __shared__ __align__(16) float dynsm[];

    int tid = threadIdx.x;
    int bx = blockIdx.x, by = blockIdx.y;
    int warp = tid >> 5, lane = tid & 31;
    int wm = warp & 1, wn = warp >> 1;
    int g = lane >> 2, qq = lane & 3;

    const float* Ab = A + (size_t)by * BM * K;
    const float* Bb = B + (size_t)bx * BN;

    int ar = tid >> 2;          // 0..63
    int ac = (tid & 3) << 2;    // 0,4,8,12
    int br = tid >> 5;          // 0..7
    int bc = (tid & 31) << 2;   // 0..124

    unsigned smBase = (unsigned)__cvta_generic_to_shared(dynsm);

    float c[4][4][4];
#pragma unroll
    for (int i = 0; i < 4; ++i)
#pragma unroll
        for (int j = 0; j < 4; ++j)
#pragma unroll
            for (int r = 0; r < 4; ++r) c[i][j][r] = 0.f;

    int nTiles = K / BK;

#pragma unroll
    for (int p = 0; p < 2; ++p) {
        if (p < nTiles) {
            unsigned base = smBase + (unsigned)(p * NN_STAGE) * 4;
            const float* ap = Ab + (size_t)ar * K + p * BK + ac;
            CP_ASYNC16(base + (unsigned)(ar * AS_STRIDE + ac) * 4, ap);
            CP_ASYNC16(base + (unsigned)((ar + 64) * AS_STRIDE + ac) * 4, ap + (size_t)64 * K);
            unsigned bbase = base + ASZ * 4;
            const float* bp = Bb + (size_t)(p * BK + br) * N + bc;
            CP_ASYNC16(bbase + (unsigned)(br * BS_STRIDE + bc) * 4, bp);
            CP_ASYNC16(bbase + (unsigned)((br + 8) * BS_STRIDE + bc) * 4, bp + (size_t)8 * N);
        }
        CP_COMMIT();
    }

    for (int t = 0; t < nTiles; ++t) {
        int stage = t % 3;
        CP_WAIT1();
        __syncthreads();

        if (t + 2 < nTiles) {
            int ps = (t + 2) % 3;
            unsigned base = smBase + (unsigned)(ps * NN_STAGE) * 4;
            const float* ap = Ab + (size_t)ar * K + (t + 2) * BK + ac;
            CP_ASYNC16(base + (unsigned)(ar * AS_STRIDE + ac) * 4, ap);
            CP_ASYNC16(base + (unsigned)((ar + 64) * AS_STRIDE + ac) * 4, ap + (size_t)64 * K);
            unsigned bbase = base + ASZ * 4;
            const float* bp = Bb + (size_t)((t + 2) * BK + br) * N + bc;
            CP_ASYNC16(bbase + (unsigned)(br * BS_STRIDE + bc) * 4, bp);
            CP_ASYNC16(bbase + (unsigned)((br + 8) * BS_STRIDE + bc) * 4, bp + (size_t)8 * N);
            CP_COMMIT();
        } else {
            CP_COMMIT();
        }

        const unsigned* As = (const unsigned*)(dynsm + stage * NN_STAGE);
        const unsigned* Bs = As + ASZ;

#pragma unroll
        for (int ks = 0; ks < BK; ks += 8) {
            unsigned a[4][4], b[4][2];
#pragma unroll
            for (int mi = 0; mi < 4; ++mi) {
                int row = wm * 64 + mi * 16 + g;
                a[mi][0] = As[row * AS_STRIDE + ks + qq];
                a[mi][1] = As[(row + 8) * AS_STRIDE + ks + qq];
                a[mi][2] = As[row * AS_STRIDE + ks + qq + 4];
                a[mi][3] = As[(row + 8) * AS_STRIDE + ks + qq + 4];
            }
#pragma unroll
            for (int ni = 0; ni < 4; ++ni) {
                int col = wn * 32 + ni * 8 + g;
                b[ni][0] = Bs[(ks + qq) * BS_STRIDE + col];
                b[ni][1] = Bs[(ks + qq + 4) * BS_STRIDE + col];
            }
#pragma unroll
            for (int mi = 0; mi < 4; ++mi)
#pragma unroll
                for (int ni = 0; ni < 4; ++ni)
                    MMA_TF32(c[mi][ni], a[mi], b[ni]);
        }
        __syncthreads();
    }

#pragma unroll
    for (int mi = 0; mi < 4; ++mi) {
        int row0 = by * BM + wm * 64 + mi * 16 + g;
#pragma unroll
        for (int ni = 0; ni < 4; ++ni) {
            int col = bx * BN + wn * 32 + ni * 8 + qq * 2;
            float v0 = c[mi][ni][0], v1 = c[mi][ni][1], v2 = c[mi][ni][2], v3 = c[mi][ni][3];
            if (RC) { v0 = rtf32(v0); v1 = rtf32(v1); v2 = rtf32(v2); v3 = rtf32(v3); }
            *(float2*)(C + (size_t)row0 * N + col)       = make_float2(v0, v1);
            *(float2*)(C + (size_t)(row0 + 8) * N + col) = make_float2(v2, v3);
        }
    }
}

// ---- NT: C[M,N] = A[M,K] @ Bt[N,K]^T ----
template<bool RC>
__global__ __launch_bounds__(256, 2) void mma_gemm_nt(
    const float* __restrict__ A, const float* __restrict__ Bt, float* __restrict__ C,
    int M, int N, int K)
{
    extern __shared__ __align__(16) float dynsm[];

    int tid = threadIdx.x;
    int bx = blockIdx.x, by = blockIdx.y;
    int warp = tid >> 5, lane = tid & 31;
    int wm = warp & 1, wn = warp >> 1;
    int g = lane >> 2, qq = lane & 3;

    const float* Ab = A  + (size_t)by * BM * K;
    const float* Bb = Bt + (size_t)bx * BN * K;

    int ar = tid >> 2;          // 0..63
    int ac = (tid & 3) << 2;    // 0,4,8,12

    unsigned smBase = (unsigned)__cvta_generic_to_shared(dynsm);

    float c[4][4][4];
#pragma unroll
    for (int i = 0; i < 4; ++i)
#pragma unroll
        for (int j = 0; j < 4; ++j)
#pragma unroll
            for (int r = 0; r < 4; ++r) c[i][j][r] = 0.f;

    int nTiles = K / BK;

#pragma unroll
    for (int p = 0; p < 2; ++p) {
        if (p < nTiles) {
            unsigned base = smBase + (unsigned)(p * NT_STAGE) * 4;
            const float* ap = Ab + (size_t)ar * K + p * BK + ac;
            CP_ASYNC16(base + (unsigned)(ar * AS_STRIDE + ac) * 4, ap);
            CP_ASYNC16(base + (unsigned)((ar + 64) * AS_STRIDE + ac) * 4, ap + (size_t)64 * K);
            unsigned bbase = base + ASZ * 4;
            const float* bp = Bb + (size_t)ar * K + p * BK + ac;
            CP_ASYNC16(bbase + (unsigned)(ar * AS_STRIDE + ac) * 4, bp);
            CP_ASYNC16(bbase + (unsigned)((ar + 64) * AS_STRIDE + ac) * 4, bp + (size_t)64 * K);
        }
        CP_COMMIT();
    }

    for (int t = 0; t < nTiles; ++t) {
        int stage = t % 3;
        CP_WAIT1();
        __syncthreads();

        if (t + 2 < nTiles) {
            int ps = (t + 2) % 3;
            unsigned base = smBase + (unsigned)(ps * NT_STAGE) * 4;
            const float* ap = Ab + (size_t)ar * K + (t + 2) * BK + ac;
            CP_ASYNC16(base + (unsigned)(ar * AS_STRIDE + ac) * 4, ap);
            CP_ASYNC16(base + (unsigned)((ar + 64) * AS_STRIDE + ac) * 4, ap + (size_t)64 * K);
            unsigned bbase = base + ASZ * 4;
            const float* bp = Bb + (size_t)ar * K + (t + 2) * BK + ac;
            CP_ASYNC16(bbase + (unsigned)(ar * AS_STRIDE + ac) * 4, bp);
            CP_ASYNC16(bbase + (unsigned)((ar + 64) * AS_STRIDE + ac) * 4, bp + (size_t)64 * K);
            CP_COMMIT();
        } else {
            CP_COMMIT();
        }

        const unsigned* As = (const unsigned*)(dynsm + stage * NT_STAGE);
        const unsigned* Bs = As + ASZ;   // [BN][AS_STRIDE]

#pragma unroll
        for (int ks = 0; ks < BK; ks += 8) {
            unsigned a[4][4], b[4][2];
#pragma unroll
            for (int mi = 0; mi < 4; ++mi) {
                int row = wm * 64 + mi * 16 + g;
                a[mi][0] = As[row * AS_STRIDE + ks + qq];
                a[mi][1] = As[(row + 8) * AS_STRIDE + ks + qq];
                a[mi][2] = As[row * AS_STRIDE + ks + qq + 4];
                a[mi][3] = As[(row + 8) * AS_STRIDE + ks + qq + 4];
            }
#pragma unroll
            for (int ni = 0; ni < 4; ++ni) {
                int col = wn * 32 + ni * 8 + g;
                b[ni][0] = Bs[col * AS_STRIDE + ks + qq];
                b[ni][1] = Bs[col * AS_STRIDE + ks + qq + 4];
            }
#pragma unroll
            for (int mi = 0; mi < 4; ++mi)
#pragma unroll
                for (int ni = 0; ni < 4; ++ni)
                    MMA_TF32(c[mi][ni], a[mi], b[ni]);
        }
        __syncthreads();
    }

#pragma unroll
    for (int mi = 0; mi < 4; ++mi) {
        int row0 = by * BM + wm * 64 + mi * 16 + g;
#pragma unroll
        for (int ni = 0; ni < 4; ++ni) {
            int col = bx * BN + wn * 32 + ni * 8 + qq * 2;
            float v0 = c[mi][ni][0], v1 = c[mi][ni][1], v2 = c[mi][ni][2], v3 = c[mi][ni][3];
            if (RC) { v0 = rtf32(v0); v1 = rtf32(v1); v2 = rtf32(v2); v3 = rtf32(v3); }
            *(float2*)(C + (size_t)row0 * N + col)       = make_float2(v0, v1);
            *(float2*)(C + (size_t)(row0 + 8) * N + col) = make_float2(v2, v3);
        }
    }
}

// ---------------- weight rounding ------------------------------------------
__global__ void round_tf32_kernel(const float* __restrict__ s, float* __restrict__ d, int n4)
{
    int i = blockIdx.x * blockDim.x + threadIdx.x;
    if (i < n4) {
        float4 v = *(const float4*)(s + (size_t)i * 4);
        v.x = rtf32(v.x); v.y = rtf32(v.y); v.z = rtf32(v.z); v.w = rtf32(v.w);
        *(float4*)(d + (size_t)i * 4) = v;
    }
}

// ---------------- RMSNorm (tf32-rounded output) -----------------------------
// If res != nullptr: x_eff = x + res, also written to hsum.
__global__ __launch_bounds__(256) void rmsnorm_kernel(
    const float* __restrict__ x, const float* __restrict__ res,
    float* __restrict__ hsum, const float* __restrict__ w, float* __restrict__ out)
{
    __shared__ float red[8];
    int row = blockIdx.x, tid = threadIdx.x;
    const float* xr = x + (size_t)row * DIM;
    float4 v[2];
    float ss = 0.f;
#pragma unroll
    for (int p = 0; p < 2; ++p) {
        int cix = p * 1024 + tid * 4;
        v[p] = *(const float4*)(xr + cix);
        if (res) {
            float4 rv = *(const float4*)(res + (size_t)row * DIM + cix);
            v[p].x += rv.x; v[p].y += rv.y; v[p].z += rv.z; v[p].w += rv.w;
            *(float4*)(hsum + (size_t)row * DIM + cix) = v[p];
        }
        ss += v[p].x * v[p].x + v[p].y * v[p].y + v[p].z * v[p].z + v[p].w * v[p].w;
    }
#pragma unroll
    for (int off = 16; off; off >>= 1) ss += __shfl_xor_sync(~0u, ss, off);
    if ((tid & 31) == 0) red[tid >> 5] = ss;
    __syncthreads();
    if (tid == 0) {
        float t = 0.f;
#pragma unroll
        for (int i = 0; i < 8; ++i) t += red[i];
        red[0] = rsqrtf(t / (float)DIM + 1e-6f);
    }
    __syncthreads();
    float inv = red[0];
    float* orow = out + (size_t)row * DIM;
#pragma unroll
    for (int p = 0; p < 2; ++p) {
        int cix = p * 1024 + tid * 4;
        float4 wv = *(const float4*)(w + cix);
        float4 o;
        o.x = rtf32(v[p].x * inv * wv.x); o.y = rtf32(v[p].y * inv * wv.y);
        o.z = rtf32(v[p].z * inv * wv.z); o.w = rtf32(v[p].w * inv * wv.w);
        *(float4*)(orow + cix) = o;
    }
}

// ---------------- RoPE (in-place on q and k) --------------------------------
__global__ void rope_kernel(float* __restrict__ q, float* __restrict__ k)
{
    int idx = blockIdx.x * blockDim.x + threadIdx.x;
    if (idx >= NROWS * NH * 64) return;
    int i   = idx & 63;
    int h   = (idx >> 6) & (NH - 1);
    int row = idx >> 10;
    int pos = row & (SQ - 1);
    float inv = (float)exp(-((double)(2 * i) / (double)HD) * 9.210340371976184);
    float ang = (float)pos * inv;
    float sn, cs;
    sincosf(ang, &sn, &cs);
    size_t base = (size_t)row * DIM + (size_t)h * HD;
    float a = q[base + i], b = q[base + i + 64];
    q[base + i]      = a * cs - b * sn;
    q[base + i + 64] = b * cs + a * sn;
    a = k[base + i]; b = k[base + i + 64];
    k[base + i]      = a * cs - b * sn;
    k[base + i + 64] = b * cs + a * sn;
}

// ---------------- Flash attention (causal), 64x64 tiles ---------------------
#define ATTN_SMEM_FLOATS (64*128 + 64*132 + 64*128 + 64*64)
#define ATTN_SMEM_BYTES  (ATTN_SMEM_FLOATS * 4)

__global__ __launch_bounds__(256) void attn_kernel(
    const float* __restrict__ Q, const float* __restrict__ K,
    const float* __restrict__ V, float* __restrict__ O)
{
    extern __shared__ float smf[];
    float* Qs = smf;
    float* Ks = smf + 8192;
    float* Vs = smf + 8192 + 8448;
    float* Ps = smf + 8192 + 8448 + 8192;

    int qt = blockIdx.x, h = blockIdx.y, b = blockIdx.z;
    int tid = threadIdx.x;
    int ty = tid >> 4, tx = tid & 15;
    int qr0 = ty * 4;
    int dc0 = tx * 8;

    const float* Qb = Q + (size_t)b * SQ * DIM + (size_t)h * HD;
    const float* Kb = K + (size_t)b * SQ * DIM + (size_t)h * HD;
    const float* Vb = V + (size_t)b * SQ * DIM + (size_t)h * HD;

    for (int i = tid; i < 64 * 32; i += 256) {
        int r = i >> 5, cix = (i & 31) << 2;
        *(float4*)&Qs[r * 128 + cix] =
            *(const float4*)(Qb + (size_t)(qt * 64 + r) * DIM + cix);
    }

    float m[4], l[4], o[4][8];
#pragma unroll
    for (int i = 0; i < 4; ++i) {
        m[i] = -3.0e38f; l[i] = 0.f;
#pragma unroll
        for (int d = 0; d < 8; ++d) o[i][d] = 0.f;
    }
    __syncthreads();

    const float SCALE = 0.08838834764831845f;

    for (int kt = 0; kt <= qt; ++kt) {
        for (int i = tid; i < 64 * 32; i += 256) {
            int r = i >> 5, cix = (i & 31) << 2;
            *(float4*)&Ks[r * 132 + cix] =
                *(const float4*)(Kb + (size_t)(kt * 64 + r) * DIM + cix);
            *(float4*)&Vs[r * 128 + cix] =
                *(const float4*)(Vb + (size_t)(kt * 64 + r) * DIM + cix);
        }
        __syncthreads();

        float s[4][4];
#pragma unroll
        for (int i = 0; i < 4; ++i)
#pragma unroll
            for (int j = 0; j < 4; ++j) s[i][j] = 0.f;

        for (int d0 = 0; d0 < HD; d0 += 4) {
            float4 kf[4];
#pragma unroll
            for (int j = 0; j < 4; ++j)
                kf[j] = *(const float4*)&Ks[(tx + 16 * j) * 132 + d0];
#pragma unroll
            for (int i = 0; i < 4; ++i) {
                float4 qf = *(const float4*)&Qs[(qr0 + i) * 128 + d0];
#pragma unroll
                for (int j = 0; j < 4; ++j) {
                    s[i][j] = fmaf(qf.x, kf[j].x, s[i][j]);
                    s[i][j] = fmaf(qf.y, kf[j].y, s[i][j]);
                    s[i][j] = fmaf(qf.z, kf[j].z, s[i][j]);
                    s[i][j] = fmaf(qf.w, kf[j].w, s[i][j]);
                }
            }
        }

#pragma unroll
        for (int i = 0; i < 4; ++i)
#pragma unroll
            for (int j = 0; j < 4; ++j) s[i][j] *= SCALE;

        if (kt == qt) {
#pragma unroll
            for (int i = 0; i < 4; ++i) {
                int qidx = qt * 64 + qr0 + i;
#pragma unroll
                for (int j = 0; j < 4; ++j) {
                    int kidx = kt * 64 + tx + 16 * j;
                    if (kidx > qidx) s[i][j] = -1e30f;
                }
            }
        }

#pragma unroll
        for (int i = 0; i < 4; ++i) {
            float mr = fmaxf(fmaxf(s[i][0], s[i][1]), fmaxf(s[i][2], s[i][3]));
#pragma unroll
            for (int off = 1; off < 16; off <<= 1)
                mr = fmaxf(mr, __shfl_xor_sync(~0u, mr, off));
            float mn = fmaxf(m[i], mr);
            float corr = __expf(m[i] - mn);
            m[i] = mn;
            float p0 = __expf(s[i][0] - mn);
            float p1 = __expf(s[i][1] - mn);
            float p2 = __expf(s[i][2] - mn);
            float p3 = __expf(s[i][3] - mn);
            float ls = p0 + p1 + p2 + p3;
#pragma unroll
            for (int off = 1; off < 16; off <<= 1)
                ls += __shfl_xor_sync(~0u, ls, off);
            l[i] = l[i] * corr + ls;
#pragma unroll
            for (int d = 0; d < 8; ++d) o[i][d] *= corr;
            Ps[(qr0 + i) * 64 + tx]      = p0;
            Ps[(qr0 + i) * 64 + tx + 16] = p1;
            Ps[(qr0 + i) * 64 + tx + 32] = p2;
            Ps[(qr0 + i) * 64 + tx + 48] = p3;
        }
        __syncthreads();

        for (int kk = 0; kk < 64; ++kk) {
            float4 v0 = *(const float4*)&Vs[kk * 128 + dc0];
            float4 v1 = *(const float4*)&Vs[kk * 128 + dc0 + 4];
#pragma unroll
            for (int i = 0; i < 4; ++i) {
                float p = Ps[(qr0 + i) * 64 + kk];
                o[i][0] = fmaf(p, v0.x, o[i][0]);
                o[i][1] = fmaf(p, v0.y, o[i][1]);
                o[i][2] = fmaf(p, v0.z, o[i][2]);
                o[i][3] = fmaf(p, v0.w, o[i][3]);
                o[i][4] = fmaf(p, v1.x, o[i][4]);
                o[i][5] = fmaf(p, v1.y, o[i][5]);
                o[i][6] = fmaf(p, v1.z, o[i][6]);
                o[i][7] = fmaf(p, v1.w, o[i][7]);
            }
        }
        __syncthreads();
    }

    // tf32-rounded output (feeds Wo GEMM)
#pragma unroll
    for (int i = 0; i < 4; ++i) {
        float inv = 1.f / l[i];
        int row = qt * 64 + qr0 + i;
        float* op = O + (size_t)(b * SQ + row) * DIM + (size_t)h * HD + dc0;
        float4 r0 = make_float4(rtf32(o[i][0] * inv), rtf32(o[i][1] * inv),
                                rtf32(o[i][2] * inv), rtf32(o[i][3] * inv));
        float4 r1 = make_float4(rtf32(o[i][4] * inv), rtf32(o[i][5] * inv),
                                rtf32(o[i][6] * inv), rtf32(o[i][7] * inv));
        *(float4*)op       = r0;
        *(float4*)(op + 4) = r1;
    }
}

// ---------------- elementwise ----------------------------------------------
__global__ void add_kernel(const float* __restrict__ a, const float* __restrict__ b,
                           float* __restrict__ c, int n)
{
    int i = blockIdx.x * blockDim.x + threadIdx.x;
    if (i < n) c[i] = a[i] + b[i];
}

__global__ void diagG_kernel(const float* __restrict__ W, float* __restrict__ diag)
{
    int j = blockIdx.x * blockDim.x + threadIdx.x;
    if (j < DLCA) {
        float s = 0.f;
        for (int i = 0; i < DIM; ++i) {
            float w = W[(size_t)i * DLCA + j];
            s = fmaf(w, w, s);
        }
        diag[j] = s;
    }
}

__global__ void lca_init_kernel(const float* __restrict__ b, float* __restrict__ u,
                                float* __restrict__ a, int n)
{
    int i = blockIdx.x * blockDim.x + threadIdx.x;
    if (i < n) {
        float uv = 0.1f * b[i];
        u[i] = uv;
        a[i] = rtf32(fmaxf(uv - 0.1f, 0.f));
    }
}

__global__ void lca_update_kernel(float* __restrict__ u, float* __restrict__ a,
                                  const float* __restrict__ b, const float* __restrict__ t2,
                                  const float* __restrict__ diag, int n)
{
    int i = blockIdx.x * blockDim.x + threadIdx.x;
    if (i < n) {
        float av  = a[i];
        float inh = t2[i] - av * diag[i & (DLCA - 1)];
        float uv  = u[i];
        uv += 0.1f * (b[i] - inh - uv);
        u[i] = uv;
        a[i] = rtf32(fmaxf(uv - 0.1f, 0.f));
    }
}

__global__ void silu_mul_kernel(float* __restrict__ g, const float* __restrict__ up, int n)
{
    int i = blockIdx.x * blockDim.x + threadIdx.x;
    if (i < n) {
        float x = g[i];
        float sig = 1.f / (1.f + expf(-x));
        g[i] = rtf32(x * sig * up[i]);
    }
}

// ---------------- launch ----------------------------------------------------
extern "C" void kernel_launch(void* const* d_in, const int* in_sizes, int n_in,
                              void* d_out, int out_size)
{
    const float* x       = (const float*)d_in[0];
    const float* w_in    = (const float*)d_in[1];
    const float* w_lcaN  = (const float*)d_in[2];
    const float* w_post  = (const float*)d_in[3];
    const float* Wq      = (const float*)d_in[4];
    const float* Wk      = (const float*)d_in[5];
    const float* Wv      = (const float*)d_in[6];
    const float* Wo      = (const float*)d_in[7];
    const float* W_lca   = (const float*)d_in[8];
    const float* W_gate  = (const float*)d_in[9];
    const float* W_up    = (const float*)d_in[10];
    const float* W_down  = (const float*)d_in[11];
    float* out = (float*)d_out;

    float *hn, *q, *k, *v, *attn, *ao, *h, *t1, *mlp, *b, *u, *a, *t2, *gate, *up, *diag;
    float *wq, *wk, *wv, *wo, *wlca, *wgate, *wup, *wdown;
    cudaGetSymbolAddress((void**)&hn,   g_hn);
    cudaGetSymbolAddress((void**)&q,    g_q);
    cudaGetSymbolAddress((void**)&k,    g_k);
    cudaGetSymbolAddress((void**)&v,    g_v);
    cudaGetSymbolAddress((void**)&attn, g_attn);
    cudaGetSymbolAddress((void**)&ao,   g_ao);
    cudaGetSymbolAddress((void**)&h,    g_h);
    cudaGetSymbolAddress((void**)&t1,   g_t1);
    cudaGetSymbolAddress((void**)&mlp,  g_mlp);
    cudaGetSymbolAddress((void**)&b,    g_b);
    cudaGetSymbolAddress((void**)&u,    g_u);
    cudaGetSymbolAddress((void**)&a,    g_a);
    cudaGetSymbolAddress((void**)&t2,   g_t2);
    cudaGetSymbolAddress((void**)&gate, g_gate);
    cudaGetSymbolAddress((void**)&up,   g_up);
    cudaGetSymbolAddress((void**)&diag, g_diag);
    cudaGetSymbolAddress((void**)&wq,    g_wq);
    cudaGetSymbolAddress((void**)&wk,    g_wk);
    cudaGetSymbolAddress((void**)&wv,    g_wv);
    cudaGetSymbolAddress((void**)&wo,    g_wo);
    cudaGetSymbolAddress((void**)&wlca,  g_wlca);
    cudaGetSymbolAddress((void**)&wgate, g_wgate);
    cudaGetSymbolAddress((void**)&wup,   g_wup);
    cudaGetSymbolAddress((void**)&wdown, g_wdown);

    cudaFuncSetAttribute(attn_kernel,
                         cudaFuncAttributeMaxDynamicSharedMemorySize, ATTN_SMEM_BYTES);
    cudaFuncSetAttribute(mma_gemm_nn<false>,
                         cudaFuncAttributeMaxDynamicSharedMemorySize, NN_SMEM_BYTES);
    cudaFuncSetAttribute(mma_gemm_nt<false>,
                         cudaFuncAttributeMaxDynamicSharedMemorySize, NT_SMEM_BYTES);
    cudaFuncSetAttribute(mma_gemm_nt<true>,
                         cudaFuncAttributeMaxDynamicSharedMemorySize, NT_SMEM_BYTES);

    const int ND  = NROWS * DIM;
    const int NL  = NROWS * DLCA;
    const int NF  = NROWS * DFF;
    dim3 gD(DIM  / BN, NROWS / BM);
    dim3 gL(DLCA / BN, NROWS / BM);
    dim3 gF(DFF  / BN, NROWS / BM);

    // ---- round weights to tf32 once per launch ----
    {
        int n4;
        n4 = DIM*DIM/4;
        round_tf32_kernel<<<(n4 + 255) / 256, 256>>>(Wq, wq, n4);
        round_tf32_kernel<<<(n4 + 255) / 256, 256>>>(Wk, wk, n4);
        round_tf32_kernel<<<(n4 + 255) / 256, 256>>>(Wv, wv, n4);
        round_tf32_kernel<<<(n4 + 255) / 256, 256>>>(Wo, wo, n4);
        n4 = DIM*DLCA/4;
        round_tf32_kernel<<<(n4 + 255) / 256, 256>>>(W_lca, wlca, n4);
        n4 = DIM*DFF/4;
        round_tf32_kernel<<<(n4 + 255) / 256, 256>>>(W_gate, wgate, n4);
        round_tf32_kernel<<<(n4 + 255) / 256, 256>>>(W_up, wup, n4);
        n4 = DFF*DIM/4;
        round_tf32_kernel<<<(n4 + 255) / 256, 256>>>(W_down, wdown, n4);
    }

    // ---- attention block ----
    rmsnorm_kernel<<<NROWS, 256>>>(x, nullptr, nullptr, w_in, hn);
    mma_gemm_nn<false><<<gD, 256, NN_SMEM_BYTES>>>(hn, wq, q, NROWS, DIM, DIM);
    mma_gemm_nn<false><<<gD, 256, NN_SMEM_BYTES>>>(hn, wk, k, NROWS, DIM, DIM);
    mma_gemm_nn<false><<<gD, 256, NN_SMEM_BYTES>>>(hn, wv, v, NROWS, DIM, DIM);
    rope_kernel<<<(NROWS * NH * 64 + 255) / 256, 256>>>(q, k);
    attn_kernel<<<dim3(SQ / 64, NH, BATCH), 256, ATTN_SMEM_BYTES>>>(q, k, v, attn);
    mma_gemm_nn<false><<<gD, 256, NN_SMEM_BYTES>>>(attn, wo, ao, NROWS, DIM, DIM);

    // ---- LCA block ----  (h = x + ao fused into rmsnorm)
    rmsnorm_kernel<<<NROWS, 256>>>(x, ao, h, w_lcaN, hn);
    mma_gemm_nn<false><<<gL, 256, NN_SMEM_BYTES>>>(hn, wlca, b, NROWS, DLCA, DIM);
    diagG_kernel<<<DLCA / 256, 256>>>(W_lca, diag);
    lca_init_kernel<<<(NL + 255) / 256, 256>>>(b, u, a, NL);
    for (int it = 0; it < 9; ++it) {
        mma_gemm_nt<true ><<<gD, 256, NT_SMEM_BYTES>>>(a, wlca, t1, NROWS, DIM, DLCA);
        mma_gemm_nn<false><<<gL, 256, NN_SMEM_BYTES>>>(t1, wlca, t2, NROWS, DLCA, DIM);
        lca_update_kernel<<<(NL + 255) / 256, 256>>>(u, a, b, t2, diag, NL);
    }
    mma_gemm_nt<false><<<gD, 256, NT_SMEM_BYTES>>>(a, wlca, h, NROWS, DIM, DLCA);

    // ---- MLP block ----
    rmsnorm_kernel<<<NROWS, 256>>>(h, nullptr, nullptr, w_post, hn);
    mma_gemm_nn<false><<<gF, 256, NN_SMEM_BYTES>>>(hn, wgate, gate, NROWS, DFF, DIM);
    mma_gemm_nn<false><<<gF, 256, NN_SMEM_BYTES>>>(hn, wup,   up,   NROWS, DFF, DIM);
    silu_mul_kernel<<<(NF + 255) / 256, 256>>>(gate, up, NF);
    mma_gemm_nn<false><<<gD, 256, NN_SMEM_BYTES>>>(gate, wdown, mlp, NROWS, DIM, DFF);
    add_kernel<<<(ND + 255) / 256, 256>>>(h, mlp, out, ND);
}

// round 6
// speedup vs baseline: 3.6348x; 1.0509x over previous
#include <cuda_runtime.h>
#include <math.h>
#include <stdint.h>

#define SQ    2048
#define DIM   2048
#define NH    16
#define HD    128
#define BATCH 2
#define NROWS 4096      // B*S
#define DLCA  4096
#define DFF   8192

// ---------------- scratch (static device globals; no allocs allowed) -------
__device__ float g_hn  [(size_t)NROWS*DIM];
__device__ float g_q   [(size_t)NROWS*DIM];
__device__ float g_k   [(size_t)NROWS*DIM];
__device__ float g_v   [(size_t)NROWS*DIM];
__device__ float g_attn[(size_t)NROWS*DIM];
__device__ float g_ao  [(size_t)NROWS*DIM];
__device__ float g_h   [(size_t)NROWS*DIM];
__device__ float g_t1  [(size_t)NROWS*DIM];
__device__ float g_mlp [(size_t)NROWS*DIM];
__device__ float g_b   [(size_t)NROWS*DLCA];
__device__ float g_u   [(size_t)NROWS*DLCA];
__device__ float g_a   [(size_t)NROWS*DLCA];
__device__ float g_t2  [(size_t)NROWS*DLCA];
__device__ float g_gate[(size_t)NROWS*DFF];
__device__ float g_up  [(size_t)NROWS*DFF];
__device__ float g_diag[DLCA];
// tf32-rounded, K-major ([N][K]) weight copies
__device__ float g_wqT [(size_t)DIM*DIM];
__device__ float g_wkT [(size_t)DIM*DIM];
__device__ float g_wvT [(size_t)DIM*DIM];
__device__ float g_woT [(size_t)DIM*DIM];
__device__ float g_wlT [(size_t)DLCA*DIM];   // W_lca^T  [4096][2048]
__device__ float g_wl  [(size_t)DIM*DLCA];   // W_lca    [2048][4096] (rounded)
__device__ float g_wgT [(size_t)DFF*DIM];
__device__ float g_wuT [(size_t)DFF*DIM];
__device__ float g_wdT [(size_t)DIM*DFF];

// ---------------- tf32 helpers ---------------------------------------------
__device__ __forceinline__ unsigned f2tf32(float f) {
    unsigned r;
    asm("cvt.rna.tf32.f32 %0, %1;" : "=r"(r) : "f"(f));
    return r;
}
__device__ __forceinline__ float rtf32(float f) { return __uint_as_float(f2tf32(f)); }

#define CP_ASYNC16(dst, src) \
    asm volatile("cp.async.cg.shared.global [%0], [%1], 16;\n" :: "r"(dst), "l"(src))
#define CP_COMMIT() asm volatile("cp.async.commit_group;\n")
#define CP_WAIT1()  asm volatile("cp.async.wait_group 1;\n" ::: "memory")

#define MMA_TF32(c, a, b) \
    asm volatile("mma.sync.aligned.m16n8k8.row.col.f32.tf32.tf32.f32 " \
                 "{%0,%1,%2,%3}, {%4,%5,%6,%7}, {%8,%9}, {%0,%1,%2,%3};" \
                 : "+f"((c)[0]), "+f"((c)[1]), "+f"((c)[2]), "+f"((c)[3]) \
                 : "r"((a)[0]), "r"((a)[1]), "r"((a)[2]), "r"((a)[3]), \
                   "r"((b)[0]), "r"((b)[1]))

// ================= TF32 GEMM v2 =============================================
// C[4096,N] = A[4096,K] @ B[N,K]^T (B K-major). CTA 128x128, 4 warps (2x2),
// warp tile 64x64, BK=32, 3-stage cp.async, single sync per tile.
#define GSTRIDE 36                    // 32 + 4 pad
#define AFL (128 * GSTRIDE)           // 4608 floats per operand tile
#define GSTG (2 * AFL)                // 9216 floats per stage
#define GEMM_SMEM_BYTES (3 * GSTG * 4)  // 110592

__global__ __launch_bounds__(128, 2) void gemm_tf32(
    const float* __restrict__ A, const float* __restrict__ B,
    float* __restrict__ C, int N, int K, int rc)
{
    extern __shared__ float sm[];
    const int tid  = threadIdx.x;
    const int warp = tid >> 5, lane = tid & 31;
    const int wm = warp & 1, wn = warp >> 1;
    const int g = lane >> 2, q = lane & 3;
    const int bx = blockIdx.x, by = blockIdx.y;

    const size_t ar0 = (size_t)by * 128;
    const size_t br0 = (size_t)bx * 128;
    unsigned smB = (unsigned)__cvta_generic_to_shared(sm);

    float c[4][8][4];
#pragma unroll
    for (int i = 0; i < 4; ++i)
#pragma unroll
        for (int j = 0; j < 8; ++j)
#pragma unroll
            for (int r = 0; r < 4; ++r) c[i][j][r] = 0.f;

    const int T = K >> 5;

    auto load_stage = [&](int t, int s) {
        unsigned base = smB + (unsigned)(s * GSTG) * 4;
        const float* Ap = A + ar0 * K + (size_t)t * 32;
        const float* Bp = B + br0 * K + (size_t)t * 32;
#pragma unroll
        for (int i = 0; i < 8; ++i) {
            int u = tid + i * 128;
            int row = u >> 3, cc = (u & 7) << 2;
            CP_ASYNC16(base + (unsigned)(row * GSTRIDE + cc) * 4,
                       Ap + (size_t)row * K + cc);
            CP_ASYNC16(base + (unsigned)(AFL + row * GSTRIDE + cc) * 4,
                       Bp + (size_t)row * K + cc);
        }
    };

    load_stage(0, 0); CP_COMMIT();
    if (T > 1) load_stage(1, 1);
    CP_COMMIT();

    for (int t = 0; t < T; ++t) {
        CP_WAIT1();
        __syncthreads();
        if (t + 2 < T) load_stage(t + 2, (t + 2) % 3);
        CP_COMMIT();

        const unsigned* As = (const unsigned*)sm + (t % 3) * GSTG;
        const unsigned* Bs = As + AFL;

#pragma unroll
        for (int ks8 = 0; ks8 < 4; ++ks8) {
            const int ks = ks8 * 8;
            unsigned a[4][4], b[8][2];
#pragma unroll
            for (int mi = 0; mi < 4; ++mi) {
                int r0 = wm * 64 + mi * 16 + g;
                a[mi][0] = As[r0 * GSTRIDE + ks + q];
                a[mi][1] = As[(r0 + 8) * GSTRIDE + ks + q];
                a[mi][2] = As[r0 * GSTRIDE + ks + q + 4];
                a[mi][3] = As[(r0 + 8) * GSTRIDE + ks + q + 4];
            }
#pragma unroll
            for (int ni = 0; ni < 8; ++ni) {
                int cn = wn * 64 + ni * 8 + g;
                b[ni][0] = Bs[cn * GSTRIDE + ks + q];
                b[ni][1] = Bs[cn * GSTRIDE + ks + q + 4];
            }
#pragma unroll
            for (int mi = 0; mi < 4; ++mi)
#pragma unroll
                for (int ni = 0; ni < 8; ++ni)
                    MMA_TF32(c[mi][ni], a[mi], b[ni]);
        }
    }

    // epilogue
#pragma unroll
    for (int mi = 0; mi < 4; ++mi) {
        int row0 = (int)ar0 + wm * 64 + mi * 16 + g;
#pragma unroll
        for (int ni = 0; ni < 8; ++ni) {
            int col = (int)br0 + wn * 64 + ni * 8 + q * 2;
            float v0 = c[mi][ni][0], v1 = c[mi][ni][1];
            float v2 = c[mi][ni][2], v3 = c[mi][ni][3];
            if (rc) { v0 = rtf32(v0); v1 = rtf32(v1); v2 = rtf32(v2); v3 = rtf32(v3); }
            *(float2*)(C + (size_t)row0 * N + col)       = make_float2(v0, v1);
            *(float2*)(C + (size_t)(row0 + 8) * N + col) = make_float2(v2, v3);
        }
    }
}

// ---------------- weight prep ----------------------------------------------
// W[K,N] f32 -> T[N][K] tf32-rounded f32
__global__ void transpose_round_kernel(const float* __restrict__ W,
                                       float* __restrict__ To, int K, int N)
{
    __shared__ float tsm[32][33];
    int n0 = blockIdx.x * 32, k0 = blockIdx.y * 32;
    int tx = threadIdx.x, ty = threadIdx.y;   // 32 x 8
#pragma unroll
    for (int i = 0; i < 4; ++i)
        tsm[ty + i * 8][tx] = W[(size_t)(k0 + ty + i * 8) * N + n0 + tx];
    __syncthreads();
#pragma unroll
    for (int i = 0; i < 4; ++i) {
        int n = n0 + ty + i * 8;
        To[(size_t)n * K + k0 + tx] = rtf32(tsm[tx][ty + i * 8]);
    }
}

__global__ void round_tf32_kernel(const float* __restrict__ s, float* __restrict__ d, int n4)
{
    int i = blockIdx.x * blockDim.x + threadIdx.x;
    if (i < n4) {
        float4 v = *(const float4*)(s + (size_t)i * 4);
        v.x = rtf32(v.x); v.y = rtf32(v.y); v.z = rtf32(v.z); v.w = rtf32(v.w);
        *(float4*)(d + (size_t)i * 4) = v;
    }
}

// ---------------- RMSNorm (tf32-rounded output) -----------------------------
__global__ __launch_bounds__(256) void rmsnorm_kernel(
    const float* __restrict__ x, const float* __restrict__ res,
    float* __restrict__ hsum, const float* __restrict__ w, float* __restrict__ out)
{
    __shared__ float red[8];
    int row = blockIdx.x, tid = threadIdx.x;
    const float* xr = x + (size_t)row * DIM;
    float4 v[2];
    float ss = 0.f;
#pragma unroll
    for (int p = 0; p < 2; ++p) {
        int cix = p * 1024 + tid * 4;
        v[p] = *(const float4*)(xr + cix);
        if (res) {
            float4 rv = *(const float4*)(res + (size_t)row * DIM + cix);
            v[p].x += rv.x; v[p].y += rv.y; v[p].z += rv.z; v[p].w += rv.w;
            *(float4*)(hsum + (size_t)row * DIM + cix) = v[p];
        }
        ss += v[p].x * v[p].x + v[p].y * v[p].y + v[p].z * v[p].z + v[p].w * v[p].w;
    }
#pragma unroll
    for (int off = 16; off; off >>= 1) ss += __shfl_xor_sync(~0u, ss, off);
    if ((tid & 31) == 0) red[tid >> 5] = ss;
    __syncthreads();
    if (tid == 0) {
        float t = 0.f;
#pragma unroll
        for (int i = 0; i < 8; ++i) t += red[i];
        red[0] = rsqrtf(t / (float)DIM + 1e-6f);
    }
    __syncthreads();
    float inv = red[0];
    float* orow = out + (size_t)row * DIM;
#pragma unroll
    for (int p = 0; p < 2; ++p) {
        int cix = p * 1024 + tid * 4;
        float4 wv = *(const float4*)(w + cix);
        float4 o;
        o.x = rtf32(v[p].x * inv * wv.x); o.y = rtf32(v[p].y * inv * wv.y);
        o.z = rtf32(v[p].z * inv * wv.z); o.w = rtf32(v[p].w * inv * wv.w);
        *(float4*)(orow + cix) = o;
    }
}

// ---------------- RoPE (in-place on q and k) --------------------------------
__global__ void rope_kernel(float* __restrict__ q, float* __restrict__ k)
{
    int idx = blockIdx.x * blockDim.x + threadIdx.x;
    if (idx >= NROWS * NH * 64) return;
    int i   = idx & 63;
    int h   = (idx >> 6) & (NH - 1);
    int row = idx >> 10;
    int pos = row & (SQ - 1);
    float inv = (float)exp(-((double)(2 * i) / (double)HD) * 9.210340371976184);
    float ang = (float)pos * inv;
    float sn, cs;
    sincosf(ang, &sn, &cs);
    size_t base = (size_t)row * DIM + (size_t)h * HD;
    float a = q[base + i], b = q[base + i + 64];
    q[base + i]      = a * cs - b * sn;
    q[base + i + 64] = b * cs + a * sn;
    a = k[base + i]; b = k[base + i + 64];
    k[base + i]      = a * cs - b * sn;
    k[base + i + 64] = b * cs + a * sn;
}

// ---------------- Flash attention (causal), 64x64 tiles ---------------------
#define ATTN_SMEM_FLOATS (64*128 + 64*132 + 64*128 + 64*64)
#define ATTN_SMEM_BYTES  (ATTN_SMEM_FLOATS * 4)

__global__ __launch_bounds__(256) void attn_kernel(
    const float* __restrict__ Q, const float* __restrict__ K,
    const float* __restrict__ V, float* __restrict__ O)
{
    extern __shared__ float smf[];
    float* Qs = smf;
    float* Ks = smf + 8192;
    float* Vs = smf + 8192 + 8448;
    float* Ps = smf + 8192 + 8448 + 8192;

    int qt = blockIdx.x, h = blockIdx.y, b = blockIdx.z;
    int tid = threadIdx.x;
    int ty = tid >> 4, tx = tid & 15;
    int qr0 = ty * 4;
    int dc0 = tx * 8;

    const float* Qb = Q + (size_t)b * SQ * DIM + (size_t)h * HD;
    const float* Kb = K + (size_t)b * SQ * DIM + (size_t)h * HD;
    const float* Vb = V + (size_t)b * SQ * DIM + (size_t)h * HD;

    for (int i = tid; i < 64 * 32; i += 256) {
        int r = i >> 5, cix = (i & 31) << 2;
        *(float4*)&Qs[r * 128 + cix] =
            *(const float4*)(Qb + (size_t)(qt * 64 + r) * DIM + cix);
    }

    float m[4], l[4], o[4][8];
#pragma unroll
    for (int i = 0; i < 4; ++i) {
        m[i] = -3.0e38f; l[i] = 0.f;
#pragma unroll
        for (int d = 0; d < 8; ++d) o[i][d] = 0.f;
    }
    __syncthreads();

    const float SCALE = 0.08838834764831845f;

    for (int kt = 0; kt <= qt; ++kt) {
        for (int i = tid; i < 64 * 32; i += 256) {
            int r = i >> 5, cix = (i & 31) << 2;
            *(float4*)&Ks[r * 132 + cix] =
                *(const float4*)(Kb + (size_t)(kt * 64 + r) * DIM + cix);
            *(float4*)&Vs[r * 128 + cix] =
                *(const float4*)(Vb + (size_t)(kt * 64 + r) * DIM + cix);
        }
        __syncthreads();

        float s[4][4];
#pragma unroll
        for (int i = 0; i < 4; ++i)
#pragma unroll
            for (int j = 0; j < 4; ++j) s[i][j] = 0.f;

        for (int d0 = 0; d0 < HD; d0 += 4) {
            float4 kf[4];
#pragma unroll
            for (int j = 0; j < 4; ++j)
                kf[j] = *(const float4*)&Ks[(tx + 16 * j) * 132 + d0];
#pragma unroll
            for (int i = 0; i < 4; ++i) {
                float4 qf = *(const float4*)&Qs[(qr0 + i) * 128 + d0];
#pragma unroll
                for (int j = 0; j < 4; ++j) {
                    s[i][j] = fmaf(qf.x, kf[j].x, s[i][j]);
                    s[i][j] = fmaf(qf.y, kf[j].y, s[i][j]);
                    s[i][j] = fmaf(qf.z, kf[j].z, s[i][j]);
                    s[i][j] = fmaf(qf.w, kf[j].w, s[i][j]);
                }
            }
        }

#pragma unroll
        for (int i = 0; i < 4; ++i)
#pragma unroll
            for (int j = 0; j < 4; ++j) s[i][j] *= SCALE;

        if (kt == qt) {
#pragma unroll
            for (int i = 0; i < 4; ++i) {
                int qidx = qt * 64 + qr0 + i;
#pragma unroll
                for (int j = 0; j < 4; ++j) {
                    int kidx = kt * 64 + tx + 16 * j;
                    if (kidx > qidx) s[i][j] = -1e30f;
                }
            }
        }

#pragma unroll
        for (int i = 0; i < 4; ++i) {
            float mr = fmaxf(fmaxf(s[i][0], s[i][1]), fmaxf(s[i][2], s[i][3]));
#pragma unroll
            for (int off = 1; off < 16; off <<= 1)
                mr = fmaxf(mr, __shfl_xor_sync(~0u, mr, off));
            float mn = fmaxf(m[i], mr);
            float corr = __expf(m[i] - mn);
            m[i] = mn;
            float p0 = __expf(s[i][0] - mn);
            float p1 = __expf(s[i][1] - mn);
            float p2 = __expf(s[i][2] - mn);
            float p3 = __expf(s[i][3] - mn);
            float ls = p0 + p1 + p2 + p3;
#pragma unroll
            for (int off = 1; off < 16; off <<= 1)
                ls += __shfl_xor_sync(~0u, ls, off);
            l[i] = l[i] * corr + ls;
#pragma unroll
            for (int d = 0; d < 8; ++d) o[i][d] *= corr;
            Ps[(qr0 + i) * 64 + tx]      = p0;
            Ps[(qr0 + i) * 64 + tx + 16] = p1;
            Ps[(qr0 + i) * 64 + tx + 32] = p2;
            Ps[(qr0 + i) * 64 + tx + 48] = p3;
        }
        __syncthreads();

        for (int kk = 0; kk < 64; ++kk) {
            float4 v0 = *(const float4*)&Vs[kk * 128 + dc0];
            float4 v1 = *(const float4*)&Vs[kk * 128 + dc0 + 4];
#pragma unroll
            for (int i = 0; i < 4; ++i) {
                float p = Ps[(qr0 + i) * 64 + kk];
                o[i][0] = fmaf(p, v0.x, o[i][0]);
                o[i][1] = fmaf(p, v0.y, o[i][1]);
                o[i][2] = fmaf(p, v0.z, o[i][2]);
                o[i][3] = fmaf(p, v0.w, o[i][3]);
                o[i][4] = fmaf(p, v1.x, o[i][4]);
                o[i][5] = fmaf(p, v1.y, o[i][5]);
                o[i][6] = fmaf(p, v1.z, o[i][6]);
                o[i][7] = fmaf(p, v1.w, o[i][7]);
            }
        }
        __syncthreads();
    }

    // tf32-rounded output (feeds Wo GEMM)
#pragma unroll
    for (int i = 0; i < 4; ++i) {
        float inv = 1.f / l[i];
        int row = qt * 64 + qr0 + i;
        float* op = O + (size_t)(b * SQ + row) * DIM + (size_t)h * HD + dc0;
        float4 r0 = make_float4(rtf32(o[i][0] * inv), rtf32(o[i][1] * inv),
                                rtf32(o[i][2] * inv), rtf32(o[i][3] * inv));
        float4 r1 = make_float4(rtf32(o[i][4] * inv), rtf32(o[i][5] * inv),
                                rtf32(o[i][6] * inv), rtf32(o[i][7] * inv));
        *(float4*)op       = r0;
        *(float4*)(op + 4) = r1;
    }
}

// ---------------- elementwise ----------------------------------------------
__global__ void add_kernel(const float* __restrict__ a, const float* __restrict__ b,
                           float* __restrict__ c, int n)
{
    int i = blockIdx.x * blockDim.x + threadIdx.x;
    if (i < n) c[i] = a[i] + b[i];
}

__global__ void diagG_kernel(const float* __restrict__ W, float* __restrict__ diag)
{
    int j = blockIdx.x * blockDim.x + threadIdx.x;
    if (j < DLCA) {
        float s = 0.f;
        for (int i = 0; i < DIM; ++i) {
            float w = W[(size_t)i * DLCA + j];
            s = fmaf(w, w, s);
        }
        diag[j] = s;
    }
}

__global__ void lca_init_kernel(const float* __restrict__ b, float* __restrict__ u,
                                float* __restrict__ a, int n)
{
    int i = blockIdx.x * blockDim.x + threadIdx.x;
    if (i < n) {
        float uv = 0.1f * b[i];
        u[i] = uv;
        a[i] = rtf32(fmaxf(uv - 0.1f, 0.f));
    }
}

__global__ void lca_update_kernel(float* __restrict__ u, float* __restrict__ a,
                                  const float* __restrict__ b, const float* __restrict__ t2,
                                  const float* __restrict__ diag, int n)
{
    int i = blockIdx.x * blockDim.x + threadIdx.x;
    if (i < n) {
        float av  = a[i];
        float inh = t2[i] - av * diag[i & (DLCA - 1)];
        float uv  = u[i];
        uv += 0.1f * (b[i] - inh - uv);
        u[i] = uv;
        a[i] = rtf32(fmaxf(uv - 0.1f, 0.f));
    }
}

__global__ void silu_mul_kernel(float* __restrict__ g, const float* __restrict__ up, int n)
{
    int i = blockIdx.x * blockDim.x + threadIdx.x;
    if (i < n) {
        float x = g[i];
        float sig = 1.f / (1.f + expf(-x));
        g[i] = rtf32(x * sig * up[i]);
    }
}

// ---------------- launch ----------------------------------------------------
extern "C" void kernel_launch(void* const* d_in, const int* in_sizes, int n_in,
                              void* d_out, int out_size)
{
    const float* x       = (const float*)d_in[0];
    const float* w_in    = (const float*)d_in[1];
    const float* w_lcaN  = (const float*)d_in[2];
    const float* w_post  = (const float*)d_in[3];
    const float* Wq      = (const float*)d_in[4];
    const float* Wk      = (const float*)d_in[5];
    const float* Wv      = (const float*)d_in[6];
    const float* Wo      = (const float*)d_in[7];
    const float* W_lca   = (const float*)d_in[8];
    const float* W_gate  = (const float*)d_in[9];
    const float* W_up    = (const float*)d_in[10];
    const float* W_down  = (const float*)d_in[11];
    float* out = (float*)d_out;

    float *hn, *q, *k, *v, *attn, *ao, *h, *t1, *mlp, *b, *u, *a, *t2, *gate, *up, *diag;
    float *wqT, *wkT, *wvT, *woT, *wlT, *wl, *wgT, *wuT, *wdT;
    cudaGetSymbolAddress((void**)&hn,   g_hn);
    cudaGetSymbolAddress((void**)&q,    g_q);
    cudaGetSymbolAddress((void**)&k,    g_k);
    cudaGetSymbolAddress((void**)&v,    g_v);
    cudaGetSymbolAddress((void**)&attn, g_attn);
    cudaGetSymbolAddress((void**)&ao,   g_ao);
    cudaGetSymbolAddress((void**)&h,    g_h);
    cudaGetSymbolAddress((void**)&t1,   g_t1);
    cudaGetSymbolAddress((void**)&mlp,  g_mlp);
    cudaGetSymbolAddress((void**)&b,    g_b);
    cudaGetSymbolAddress((void**)&u,    g_u);
    cudaGetSymbolAddress((void**)&a,    g_a);
    cudaGetSymbolAddress((void**)&t2,   g_t2);
    cudaGetSymbolAddress((void**)&gate, g_gate);
    cudaGetSymbolAddress((void**)&up,   g_up);
    cudaGetSymbolAddress((void**)&diag, g_diag);
    cudaGetSymbolAddress((void**)&wqT,  g_wqT);
    cudaGetSymbolAddress((void**)&wkT,  g_wkT);
    cudaGetSymbolAddress((void**)&wvT,  g_wvT);
    cudaGetSymbolAddress((void**)&woT,  g_woT);
    cudaGetSymbolAddress((void**)&wlT,  g_wlT);
    cudaGetSymbolAddress((void**)&wl,   g_wl);
    cudaGetSymbolAddress((void**)&wgT,  g_wgT);
    cudaGetSymbolAddress((void**)&wuT,  g_wuT);
    cudaGetSymbolAddress((void**)&wdT,  g_wdT);

    cudaFuncSetAttribute(attn_kernel,
                         cudaFuncAttributeMaxDynamicSharedMemorySize, ATTN_SMEM_BYTES);
    cudaFuncSetAttribute(gemm_tf32,
                         cudaFuncAttributeMaxDynamicSharedMemorySize, GEMM_SMEM_BYTES);

    const int ND = NROWS * DIM;
    const int NL = NROWS * DLCA;
    const int NF = NROWS * DFF;
    dim3 tp(32, 8);

    // ---- weight prep: transpose + tf32 round (K-major [N][K]) ----
    transpose_round_kernel<<<dim3(DIM/32,  DIM/32), tp>>>(Wq,     wqT, DIM, DIM);
    transpose_round_kernel<<<dim3(DIM/32,  DIM/32), tp>>>(Wk,     wkT, DIM, DIM);
    transpose_round_kernel<<<dim3(DIM/32,  DIM/32), tp>>>(Wv,     wvT, DIM, DIM);
    transpose_round_kernel<<<dim3(DIM/32,  DIM/32), tp>>>(Wo,     woT, DIM, DIM);
    transpose_round_kernel<<<dim3(DLCA/32, DIM/32), tp>>>(W_lca,  wlT, DIM, DLCA);
    round_tf32_kernel<<<(DIM*DLCA/4 + 255)/256, 256>>>(W_lca, wl, DIM*DLCA/4);
    transpose_round_kernel<<<dim3(DFF/32,  DIM/32), tp>>>(W_gate, wgT, DIM, DFF);
    transpose_round_kernel<<<dim3(DFF/32,  DIM/32), tp>>>(W_up,   wuT, DIM, DFF);
    transpose_round_kernel<<<dim3(DIM/32,  DFF/32), tp>>>(W_down, wdT, DFF, DIM);
    diagG_kernel<<<DLCA / 256, 256>>>(W_lca, diag);

    dim3 gD(DIM / 128,  NROWS / 128);   // (16, 32)
    dim3 gL(DLCA / 128, NROWS / 128);   // (32, 32)
    dim3 gF(DFF / 128,  NROWS / 128);   // (64, 32)

    // ---- attention block ----
    rmsnorm_kernel<<<NROWS, 256>>>(x, nullptr, nullptr, w_in, hn);
    gemm_tf32<<<gD, 128, GEMM_SMEM_BYTES>>>(hn, wqT, q, DIM, DIM, 0);
    gemm_tf32<<<gD, 128, GEMM_SMEM_BYTES>>>(hn, wkT, k, DIM, DIM, 0);
    gemm_tf32<<<gD, 128, GEMM_SMEM_BYTES>>>(hn, wvT, v, DIM, DIM, 0);
    rope_kernel<<<(NROWS * NH * 64 + 255) / 256, 256>>>(q, k);
    attn_kernel<<<dim3(SQ / 64, NH, BATCH), 256, ATTN_SMEM_BYTES>>>(q, k, v, attn);
    gemm_tf32<<<gD, 128, GEMM_SMEM_BYTES>>>(attn, woT, ao, DIM, DIM, 0);

    // ---- LCA block ----  (h = x + ao fused into rmsnorm)
    rmsnorm_kernel<<<NROWS, 256>>>(x, ao, h, w_lcaN, hn);
    gemm_tf32<<<gL, 128, GEMM_SMEM_BYTES>>>(hn, wlT, b, DLCA, DIM, 0);
    lca_init_kernel<<<(NL + 255) / 256, 256>>>(b, u, a, NL);
    for (int it = 0; it < 9; ++it) {
        gemm_tf32<<<gD, 128, GEMM_SMEM_BYTES>>>(a,  wl,  t1, DIM,  DLCA, 1);
        gemm_tf32<<<gL, 128, GEMM_SMEM_BYTES>>>(t1, wlT, t2, DLCA, DIM,  0);
        lca_update_kernel<<<(NL + 255) / 256, 256>>>(u, a, b, t2, diag, NL);
    }
    gemm_tf32<<<gD, 128, GEMM_SMEM_BYTES>>>(a, wl, h, DIM, DLCA, 0);

    // ---- MLP block ----
    rmsnorm_kernel<<<NROWS, 256>>>(h, nullptr, nullptr, w_post, hn);
    gemm_tf32<<<gF, 128, GEMM_SMEM_BYTES>>>(hn, wgT, gate, DFF, DIM, 0);
    gemm_tf32<<<gF, 128, GEMM_SMEM_BYTES>>>(hn, wuT, up,   DFF, DIM, 0);
    silu_mul_kernel<<<(NF + 255) / 256, 256>>>(gate, up, NF);
    gemm_tf32<<<gD, 128, GEMM_SMEM_BYTES>>>(gate, wdT, mlp, DIM, DFF, 0);
    add_kernel<<<(ND + 255) / 256, 256>>>(h, mlp, out, ND);
}